// round 9
// baseline (speedup 1.0000x reference)
#include <cuda_runtime.h>
#include <cuda_fp16.h>
#include <cstdint>

// Problem constants
#define NB 2
#define NS 2048
#define ND 1024
#define NH 16
#define NDH 64
#define NM (NB * NS)

// Scratch (device globals: allocation-free)
__device__ __half g_q[(size_t)NB * NH * NS * NDH];     // [b,h,s,dh]
__device__ __half g_k[(size_t)NB * NH * NS * NDH];     // [b,h,s,dh]
__device__ __half g_v[(size_t)NB * NH * NS * NDH];     // [b,h,dh,s]  TRANSPOSED
__device__ float  g_attn[(size_t)NB * NS * ND];

// ---------------- helpers ----------------
__device__ __forceinline__ uint32_t f2h2(float a, float b) {
    __half2 h = __floats2half2_rn(a, b);
    return *reinterpret_cast<uint32_t*>(&h);
}

// D(16x8,f32) += A(16x16,f16) * B(16x8,f16)
__device__ __forceinline__ void mma_f16(float c[4], const uint32_t a[4], const uint32_t b[2]) {
    asm volatile(
        "mma.sync.aligned.m16n8k16.row.col.f32.f16.f16.f32 "
        "{%0,%1,%2,%3}, {%4,%5,%6,%7}, {%8,%9}, {%0,%1,%2,%3};"
        : "+f"(c[0]), "+f"(c[1]), "+f"(c[2]), "+f"(c[3])
        : "r"(a[0]), "r"(a[1]), "r"(a[2]), "r"(a[3]), "r"(b[0]), "r"(b[1]));
}

__device__ __forceinline__ void ldm_x4(uint32_t* r, const uint32_t* p) {
    uint32_t a = (uint32_t)__cvta_generic_to_shared(p);
    asm volatile("ldmatrix.sync.aligned.m8n8.x4.shared.b16 {%0,%1,%2,%3}, [%4];"
        : "=r"(r[0]), "=r"(r[1]), "=r"(r[2]), "=r"(r[3]) : "r"(a));
}
__device__ __forceinline__ void ldm_x2(uint32_t* r, const uint32_t* p) {
    uint32_t a = (uint32_t)__cvta_generic_to_shared(p);
    asm volatile("ldmatrix.sync.aligned.m8n8.x2.shared.b16 {%0,%1}, [%2];"
        : "=r"(r[0]), "=r"(r[1]) : "r"(a));
}

__device__ __forceinline__ void cpa16(void* smem, const void* g) {
    uint32_t s = (uint32_t)__cvta_generic_to_shared(smem);
    asm volatile("cp.async.cg.shared.global [%0], [%1], 16;" :: "r"(s), "l"(g));
}
__device__ __forceinline__ void cpa_commit() { asm volatile("cp.async.commit_group;"); }
__device__ __forceinline__ void cpa_wait0() { asm volatile("cp.async.wait_group 0;" ::: "memory"); }
__device__ __forceinline__ void cpa_wait1() { asm volatile("cp.async.wait_group 1;" ::: "memory"); }

// ---------------------------------------------------------------------------
// GEMM (R8 ldmatrix version — measured win): C = A @ W^T + bias, fp16 TC.
// BM=BN=128, BK=32, 256 threads. MODE 0: f32 row-major. MODE 1: half
// [b,h,s,dh]. MODE 2: half [b,h,dh,s] (transposed, for V).
// ---------------------------------------------------------------------------
template <int MODE>
__global__ __launch_bounds__(256) void gemm_f16(
    const float* __restrict__ A, const float* __restrict__ W,
    const float* __restrict__ bias, void* __restrict__ outv)
{
    __shared__ uint32_t As[128 * 20];
    __shared__ uint32_t Ws[128 * 20];

    const int tid = threadIdx.x;
    const int wid = tid >> 5, lane = tid & 31;
    const int g = lane >> 2, t = lane & 3;
    const int wm = (wid & 3) * 32;
    const int wn = (wid >> 2) * 64;
    const int bm = blockIdx.y * 128, bn = blockIdx.x * 128;

    const int lr = tid >> 1;
    const int lp = (tid & 1) * 8;

    const int la16 = lane & 15;
    const int lac  = (lane >> 4) * 4;
    const int lb8  = lane & 7;
    const int lbc  = ((lane >> 3) & 1) * 4;

    float c[2][8][4];
#pragma unroll
    for (int i = 0; i < 2; i++)
#pragma unroll
        for (int j = 0; j < 8; j++)
#pragma unroll
            for (int q = 0; q < 4; q++) c[i][j][q] = 0.f;

    const float* aptr = A + (size_t)(bm + lr) * ND + lp * 2;
    const float* wptr = W + (size_t)(bn + lr) * ND + lp * 2;

    for (int k0 = 0; k0 < ND; k0 += 32) {
        float4 a0 = *(const float4*)(aptr + k0);
        float4 a1 = *(const float4*)(aptr + k0 + 4);
        float4 a2 = *(const float4*)(aptr + k0 + 8);
        float4 a3 = *(const float4*)(aptr + k0 + 12);
        float4 w0 = *(const float4*)(wptr + k0);
        float4 w1 = *(const float4*)(wptr + k0 + 4);
        float4 w2 = *(const float4*)(wptr + k0 + 8);
        float4 w3 = *(const float4*)(wptr + k0 + 12);
        __syncthreads();
        *(uint4*)&As[lr * 20 + lp] =
            make_uint4(f2h2(a0.x, a0.y), f2h2(a0.z, a0.w), f2h2(a1.x, a1.y), f2h2(a1.z, a1.w));
        *(uint4*)&As[lr * 20 + lp + 4] =
            make_uint4(f2h2(a2.x, a2.y), f2h2(a2.z, a2.w), f2h2(a3.x, a3.y), f2h2(a3.z, a3.w));
        *(uint4*)&Ws[lr * 20 + lp] =
            make_uint4(f2h2(w0.x, w0.y), f2h2(w0.z, w0.w), f2h2(w1.x, w1.y), f2h2(w1.z, w1.w));
        *(uint4*)&Ws[lr * 20 + lp + 4] =
            make_uint4(f2h2(w2.x, w2.y), f2h2(w2.z, w2.w), f2h2(w3.x, w3.y), f2h2(w3.z, w3.w));
        __syncthreads();

#pragma unroll
        for (int ch = 0; ch < 2; ch++) {
            uint32_t af[2][4];
            ldm_x4(af[0], &As[(wm + la16)      * 20 + ch * 8 + lac]);
            ldm_x4(af[1], &As[(wm + 16 + la16) * 20 + ch * 8 + lac]);
#pragma unroll
            for (int nt = 0; nt < 8; nt++) {
                uint32_t bf[2];
                ldm_x2(bf, &Ws[(wn + nt * 8 + lb8) * 20 + ch * 8 + lbc]);
                mma_f16(c[0][nt], af[0], bf);
                mma_f16(c[1][nt], af[1], bf);
            }
        }
    }

#pragma unroll
    for (int mt = 0; mt < 2; mt++) {
#pragma unroll
        for (int rr = 0; rr < 2; rr++) {
            const int m = bm + wm + mt * 16 + g + rr * 8;
            const int b = m >> 11, sIdx = m & (NS - 1);
#pragma unroll
            for (int nt = 0; nt < 8; nt++) {
                const int col = bn + wn + nt * 8 + 2 * t;
                const float vx = c[mt][nt][rr * 2 + 0] + bias[col];
                const float vy = c[mt][nt][rr * 2 + 1] + bias[col + 1];
                if (MODE == 0) {
                    *(float2*)&((float*)outv)[(size_t)m * ND + col] = make_float2(vx, vy);
                } else if (MODE == 1) {
                    const int h = col >> 6, dh = col & 63;
                    *(uint32_t*)&((__half*)outv)[((size_t)(b * NH + h) * NS + sIdx) * NDH + dh] =
                        f2h2(vx, vy);
                } else {
                    const int h = col >> 6, dh = col & 63;
                    __half* o = (__half*)outv + ((size_t)(b * NH + h) * NDH) * NS;
                    o[(size_t)dh * NS + sIdx]       = __float2half_rn(vx);
                    o[(size_t)(dh + 1) * NS + sIdx] = __float2half_rn(vy);
                }
            }
        }
    }
}

// ---------------------------------------------------------------------------
// Attention v9 = v7 core (scalar fragment LDS — measured best) + fused
// normalization epilogue: block re-reads its own just-written (L2-hot)
// weights slab and rescales by 1/rowsum in place. norm_w kernel eliminated.
// Block = 64 q rows, 256 threads (8 warps: 4m x 2n). Warp tile 16q x 32k.
// ---------------------------------------------------------------------------
#define NT_TILES (NS / 64)
#define KST 36
__global__ __launch_bounds__(256) void attn_f16(
    const int* __restrict__ mask, float* __restrict__ wout)
{
    extern __shared__ uint32_t dsm[];
    uint32_t* KsB = dsm;                       // 2 x 64*36
    uint32_t* VsB = dsm + 2 * 64 * KST;        // 2 x 64*36
    uint32_t* Es  = VsB + 2 * 64 * KST;        // 64*36
    float*    red = (float*)(Es + 64 * KST);   // 128 floats

    const int b = blockIdx.z, h = blockIdx.y;
    const int q0 = blockIdx.x * 64;
    const int tid = threadIdx.x;
    const int wid = tid >> 5, lane = tid & 31;
    const int g = lane >> 2, t = lane & 3;
    const int wm = (wid & 3) * 16;             // q rows within block
    const int wn = (wid >> 2) * 32;            // key cols (S) / dh cols (PV)
    const size_t bh = (size_t)(b * NH + h);

    const int sr = tid >> 2;                   // staging row 0..63
    const int sch = tid & 3;                   // staging chunk 0..3

    // Stage Q (half, 64x64) into Es
    const __half* qptr = g_q + (bh * NS + q0) * NDH;
    cpa16(&Es[sr * KST + sch * 4],      qptr + sr * NDH + sch * 8);
    cpa16(&Es[sr * KST + sch * 4 + 16], qptr + sr * NDH + sch * 8 + 32);
    cpa_commit();
    cpa_wait0();
    __syncthreads();

    // Q fragments: 4 k16-chunks x 4 regs (scalar LDS — v7 pattern)
    uint32_t qf[4][4];
#pragma unroll
    for (int ch = 0; ch < 4; ch++) {
        qf[ch][0] = Es[(wm + g)     * KST + ch * 8 + t];
        qf[ch][1] = Es[(wm + g + 8) * KST + ch * 8 + t];
        qf[ch][2] = Es[(wm + g)     * KST + ch * 8 + t + 4];
        qf[ch][3] = Es[(wm + g + 8) * KST + ch * 8 + t + 4];
    }
    __syncthreads();   // qf built before Es is reused for E

    float cacc[4][4];
#pragma unroll
    for (int nt = 0; nt < 4; nt++)
#pragma unroll
        for (int q = 0; q < 4; q++) cacc[nt][q] = 0.f;
    float rs0 = 0.f, rs1 = 0.f;

    const int* mbase = mask + (size_t)b * NS * NS;
    float* wbase = wout ? wout + bh * NS * NS : nullptr;
    const __half* kbase = g_k + bh * NS * NDH;         // [s][dh]
    const __half* vbase = g_v + bh * (size_t)NDH * NS; // [dh][s]

    // Prologue: tile 0 into buffer 0. K rows = keys; V rows = dh.
    cpa16(&KsB[sr * KST + sch * 4],      kbase + sr * NDH + sch * 8);
    cpa16(&KsB[sr * KST + sch * 4 + 16], kbase + sr * NDH + sch * 8 + 32);
    cpa16(&VsB[sr * KST + sch * 4],      vbase + (size_t)sr * NS + sch * 8);
    cpa16(&VsB[sr * KST + sch * 4 + 16], vbase + (size_t)sr * NS + sch * 8 + 32);
    cpa_commit();

    for (int kt = 0; kt < NT_TILES; kt++) {
        if (kt + 1 < NT_TILES) {
            const int nb = (kt + 1) & 1;
            const __half* kp = kbase + (size_t)(kt + 1) * 64 * NDH;
            const __half* vp = vbase + (size_t)(kt + 1) * 64;
            uint32_t* kd = KsB + nb * 64 * KST;
            uint32_t* vd = VsB + nb * 64 * KST;
            cpa16(&kd[sr * KST + sch * 4],      kp + sr * NDH + sch * 8);
            cpa16(&kd[sr * KST + sch * 4 + 16], kp + sr * NDH + sch * 8 + 32);
            cpa16(&vd[sr * KST + sch * 4],      vp + (size_t)sr * NS + sch * 8);
            cpa16(&vd[sr * KST + sch * 4 + 16], vp + (size_t)sr * NS + sch * 8 + 32);
            cpa_commit();
            cpa_wait1();
        } else {
            cpa_wait0();
        }
        __syncthreads();

        const uint32_t* Ks = KsB + (kt & 1) * 64 * KST;
        const uint32_t* Vs = VsB + (kt & 1) * 64 * KST;

        // S phase (v7): scalar B-fragment loads, 4 independent chains
        float lg[4][4];
#pragma unroll
        for (int nt = 0; nt < 4; nt++)
#pragma unroll
            for (int q = 0; q < 4; q++) lg[nt][q] = 0.f;
#pragma unroll
        for (int ch = 0; ch < 4; ch++) {
#pragma unroll
            for (int nt = 0; nt < 4; nt++) {
                const int kc = wn + nt * 8;
                uint32_t bf[2];
                bf[0] = Ks[(kc + g) * KST + ch * 8 + t];
                bf[1] = Ks[(kc + g) * KST + ch * 8 + t + 4];
                mma_f16(lg[nt], qf[ch], bf);
            }
        }

        // mask + exp + unnormalized weight write + rowsum; E -> Es (half2)
        const int qr0 = q0 + wm + g, qr1 = qr0 + 8;
#pragma unroll
        for (int nt = 0; nt < 4; nt++) {
            const int klocal = wn + nt * 8 + 2 * t;
            const int kcg = kt * 64 + klocal;
            int2 m0 = *(const int2*)(mbase + (size_t)qr0 * NS + kcg);
            int2 m1 = *(const int2*)(mbase + (size_t)qr1 * NS + kcg);
            float e0 = m0.x ? 0.f : __expf(lg[nt][0] * 0.125f);
            float e1 = m0.y ? 0.f : __expf(lg[nt][1] * 0.125f);
            float e2 = m1.x ? 0.f : __expf(lg[nt][2] * 0.125f);
            float e3 = m1.y ? 0.f : __expf(lg[nt][3] * 0.125f);
            rs0 += e0 + e1;
            rs1 += e2 + e3;
            if (wbase) {
                *(float2*)&wbase[(size_t)qr0 * NS + kcg] = make_float2(e0, e1);
                *(float2*)&wbase[(size_t)qr1 * NS + kcg] = make_float2(e2, e3);
            }
            const int pair = (klocal >> 1);
            Es[(wm + g)     * KST + pair] = f2h2(e0, e1);
            Es[(wm + g + 8) * KST + pair] = f2h2(e2, e3);
        }
        __syncthreads();   // all E tiles visible

        // PV (v7): scalar fragment loads
#pragma unroll
        for (int ch = 0; ch < 4; ch++) {
            uint32_t af[4];
            af[0] = Es[(wm + g)     * KST + ch * 8 + t];
            af[1] = Es[(wm + g + 8) * KST + ch * 8 + t];
            af[2] = Es[(wm + g)     * KST + ch * 8 + t + 4];
            af[3] = Es[(wm + g + 8) * KST + ch * 8 + t + 4];
#pragma unroll
            for (int nt = 0; nt < 4; nt++) {
                const int dc = wn + nt * 8 + g;
                uint32_t bf[2];
                bf[0] = Vs[dc * KST + ch * 8 + t];
                bf[1] = Vs[dc * KST + ch * 8 + t + 4];
                mma_f16(cacc[nt], af, bf);
            }
        }
        __syncthreads();   // compute done before buffers/Es overwritten
    }

    // Rowsums: quad-reduce over t, combine the two n-warps via smem
    rs0 += __shfl_xor_sync(0xffffffffu, rs0, 1);
    rs0 += __shfl_xor_sync(0xffffffffu, rs0, 2);
    rs1 += __shfl_xor_sync(0xffffffffu, rs1, 1);
    rs1 += __shfl_xor_sync(0xffffffffu, rs1, 2);
    if (t == 0) {
        const int half = (wid >= 4) ? 64 : 0;
        red[half + wm + g]     = rs0;
        red[half + wm + g + 8] = rs1;
    }
    __syncthreads();
    const float tot0 = red[wm + g]     + red[64 + wm + g];
    const float tot1 = red[wm + g + 8] + red[64 + wm + g + 8];
    const float inv0 = 1.f / tot0, inv1 = 1.f / tot1;

    // Normalized attn, concat layout (b, s, h*64 + dh), f32
    const int q = q0 + wm + g;
#pragma unroll
    for (int nt = 0; nt < 4; nt++) {
        const int dh = wn + nt * 8 + 2 * t;
        *(float2*)&g_attn[((size_t)b * NS + q) * ND + h * NDH + dh] =
            make_float2(cacc[nt][0] * inv0, cacc[nt][1] * inv0);
        *(float2*)&g_attn[((size_t)b * NS + q + 8) * ND + h * NDH + dh] =
            make_float2(cacc[nt][2] * inv1, cacc[nt][3] * inv1);
    }

    // Fused weight normalization: rescale this thread's OWN writes (L2-hot).
    // Same thread, same addresses -> no fence needed; math identical to the
    // old norm_w kernel (e * inv in f32).
    if (wbase) {
        float* r0p = wbase + (size_t)(q0 + wm + g) * NS;
        float* r1p = wbase + (size_t)(q0 + wm + g + 8) * NS;
#pragma unroll 4
        for (int kt = 0; kt < NT_TILES; kt++) {
#pragma unroll
            for (int nt = 0; nt < 4; nt++) {
                const int kcg = kt * 64 + wn + nt * 8 + 2 * t;
                float2 w0 = *(float2*)&r0p[kcg];
                float2 w1 = *(float2*)&r1p[kcg];
                w0.x *= inv0; w0.y *= inv0;
                w1.x *= inv1; w1.y *= inv1;
                *(float2*)&r0p[kcg] = w0;
                *(float2*)&r1p[kcg] = w1;
            }
        }
    }
}

extern "C" void kernel_launch(void* const* d_in, const int* in_sizes, int n_in,
                              void* d_out, int out_size)
{
    const float* Xq  = (const float*)d_in[0];
    const float* Xk  = (const float*)d_in[1];
    const float* Xv  = (const float*)d_in[2];
    const int*   msk = (const int*)d_in[3];
    const float* Wq  = (const float*)d_in[4];
    const float* bq  = (const float*)d_in[5];
    const float* Wk  = (const float*)d_in[6];
    const float* bk  = (const float*)d_in[7];
    const float* Wv  = (const float*)d_in[8];
    const float* bv  = (const float*)d_in[9];
    const float* Wo  = (const float*)d_in[10];
    const float* bo  = (const float*)d_in[11];

    float* out = (float*)d_out;
    const size_t n_attn = (size_t)NB * NS * ND;
    const size_t n_w    = (size_t)NB * NH * NS * NS;

    float* attn_dst = nullptr;
    float* w_dst = nullptr;
    if ((size_t)out_size >= n_attn + n_w) { attn_dst = out; w_dst = out + n_attn; }
    else if ((size_t)out_size >= n_w)     { w_dst = out; }
    else                                  { attn_dst = out; }

    __half *pq, *pk, *pv;
    float *pa;
    cudaGetSymbolAddress((void**)&pq, g_q);
    cudaGetSymbolAddress((void**)&pk, g_k);
    cudaGetSymbolAddress((void**)&pv, g_v);
    cudaGetSymbolAddress((void**)&pa, g_attn);

    dim3 ggrid(ND / 128, NM / 128);   // (8, 32)
    gemm_f16<1><<<ggrid, 256>>>(Xq, Wq, bq, pq);
    gemm_f16<1><<<ggrid, 256>>>(Xk, Wk, bk, pk);
    gemm_f16<2><<<ggrid, 256>>>(Xv, Wv, bv, pv);   // V transposed [b,h,dh,s]

    const int attn_smem = (5 * 64 * KST) * 4 + 128 * 4 + 256;  // ~46.8 KB
    cudaFuncSetAttribute(attn_f16, cudaFuncAttributeMaxDynamicSharedMemorySize, attn_smem);
    attn_f16<<<dim3(NS / 64, NH, NB), 256, attn_smem>>>(msk, w_dst);

    if (attn_dst) gemm_f16<0><<<ggrid, 256>>>(pa, Wo, bo, attn_dst);
}

// round 10
// speedup vs baseline: 1.1896x; 1.1896x over previous
#include <cuda_runtime.h>
#include <cuda_fp16.h>
#include <cstdint>

// Problem constants
#define NB 2
#define NS 2048
#define ND 1024
#define NH 16
#define NDH 64
#define NM (NB * NS)

// Scratch (device globals: allocation-free)
__device__ __half g_q[(size_t)NB * NH * NS * NDH];     // [b,h,s,dh]
__device__ __half g_k[(size_t)NB * NH * NS * NDH];     // [b,h,s,dh]
__device__ __half g_v[(size_t)NB * NH * NS * NDH];     // [b,h,dh,s]  TRANSPOSED
__device__ float  g_attn[(size_t)NB * NS * ND];
__device__ float  g_rowsum[(size_t)NB * NH * NS];

// ---------------- helpers ----------------
__device__ __forceinline__ uint32_t f2h2(float a, float b) {
    __half2 h = __floats2half2_rn(a, b);
    return *reinterpret_cast<uint32_t*>(&h);
}

__device__ __forceinline__ void mma_f16(float c[4], const uint32_t a[4], const uint32_t b[2]) {
    asm volatile(
        "mma.sync.aligned.m16n8k16.row.col.f32.f16.f16.f32 "
        "{%0,%1,%2,%3}, {%4,%5,%6,%7}, {%8,%9}, {%0,%1,%2,%3};"
        : "+f"(c[0]), "+f"(c[1]), "+f"(c[2]), "+f"(c[3])
        : "r"(a[0]), "r"(a[1]), "r"(a[2]), "r"(a[3]), "r"(b[0]), "r"(b[1]));
}

__device__ __forceinline__ void ldm_x4(uint32_t* r, const uint32_t* p) {
    uint32_t a = (uint32_t)__cvta_generic_to_shared(p);
    asm volatile("ldmatrix.sync.aligned.m8n8.x4.shared.b16 {%0,%1,%2,%3}, [%4];"
        : "=r"(r[0]), "=r"(r[1]), "=r"(r[2]), "=r"(r[3]) : "r"(a));
}
__device__ __forceinline__ void ldm_x2(uint32_t* r, const uint32_t* p) {
    uint32_t a = (uint32_t)__cvta_generic_to_shared(p);
    asm volatile("ldmatrix.sync.aligned.m8n8.x2.shared.b16 {%0,%1}, [%2];"
        : "=r"(r[0]), "=r"(r[1]) : "r"(a));
}

__device__ __forceinline__ void cpa16(void* smem, const void* g) {
    uint32_t s = (uint32_t)__cvta_generic_to_shared(smem);
    asm volatile("cp.async.cg.shared.global [%0], [%1], 16;" :: "r"(s), "l"(g));
}
__device__ __forceinline__ void cpa_commit() { asm volatile("cp.async.commit_group;"); }
__device__ __forceinline__ void cpa_wait0() { asm volatile("cp.async.wait_group 0;" ::: "memory"); }
__device__ __forceinline__ void cpa_wait1() { asm volatile("cp.async.wait_group 1;" ::: "memory"); }

// ---------------------------------------------------------------------------
// Batched QKV projection GEMM (ldmatrix): one launch, grid.z selects problem.
// z=0 (Q), z=1 (K): half out [b,h,s,dh]. z=2 (V): half out [b,h,dh,s].
// ---------------------------------------------------------------------------
struct P3 {
    const float* A[3];
    const float* W[3];
    const float* B[3];
    __half* O[3];
};

__global__ __launch_bounds__(256) void gemm_qkv(P3 p)
{
    __shared__ uint32_t As[128 * 20];
    __shared__ uint32_t Ws[128 * 20];

    const int z = blockIdx.z;
    const float* __restrict__ A = p.A[z];
    const float* __restrict__ W = p.W[z];
    const float* __restrict__ bias = p.B[z];
    __half* __restrict__ out = p.O[z];

    const int tid = threadIdx.x;
    const int wid = tid >> 5, lane = tid & 31;
    const int g = lane >> 2, t = lane & 3;
    const int wm = (wid & 3) * 32;
    const int wn = (wid >> 2) * 64;
    const int bm = blockIdx.y * 128, bn = blockIdx.x * 128;

    const int lr = tid >> 1;
    const int lp = (tid & 1) * 8;

    const int la16 = lane & 15;
    const int lac  = (lane >> 4) * 4;
    const int lb8  = lane & 7;
    const int lbc  = ((lane >> 3) & 1) * 4;

    float c[2][8][4];
#pragma unroll
    for (int i = 0; i < 2; i++)
#pragma unroll
        for (int j = 0; j < 8; j++)
#pragma unroll
            for (int q = 0; q < 4; q++) c[i][j][q] = 0.f;

    const float* aptr = A + (size_t)(bm + lr) * ND + lp * 2;
    const float* wptr = W + (size_t)(bn + lr) * ND + lp * 2;

    for (int k0 = 0; k0 < ND; k0 += 32) {
        float4 a0 = *(const float4*)(aptr + k0);
        float4 a1 = *(const float4*)(aptr + k0 + 4);
        float4 a2 = *(const float4*)(aptr + k0 + 8);
        float4 a3 = *(const float4*)(aptr + k0 + 12);
        float4 w0 = *(const float4*)(wptr + k0);
        float4 w1 = *(const float4*)(wptr + k0 + 4);
        float4 w2 = *(const float4*)(wptr + k0 + 8);
        float4 w3 = *(const float4*)(wptr + k0 + 12);
        __syncthreads();
        *(uint4*)&As[lr * 20 + lp] =
            make_uint4(f2h2(a0.x, a0.y), f2h2(a0.z, a0.w), f2h2(a1.x, a1.y), f2h2(a1.z, a1.w));
        *(uint4*)&As[lr * 20 + lp + 4] =
            make_uint4(f2h2(a2.x, a2.y), f2h2(a2.z, a2.w), f2h2(a3.x, a3.y), f2h2(a3.z, a3.w));
        *(uint4*)&Ws[lr * 20 + lp] =
            make_uint4(f2h2(w0.x, w0.y), f2h2(w0.z, w0.w), f2h2(w1.x, w1.y), f2h2(w1.z, w1.w));
        *(uint4*)&Ws[lr * 20 + lp + 4] =
            make_uint4(f2h2(w2.x, w2.y), f2h2(w2.z, w2.w), f2h2(w3.x, w3.y), f2h2(w3.z, w3.w));
        __syncthreads();

#pragma unroll
        for (int ch = 0; ch < 2; ch++) {
            uint32_t af[2][4];
            ldm_x4(af[0], &As[(wm + la16)      * 20 + ch * 8 + lac]);
            ldm_x4(af[1], &As[(wm + 16 + la16) * 20 + ch * 8 + lac]);
#pragma unroll
            for (int nt = 0; nt < 8; nt++) {
                uint32_t bf[2];
                ldm_x2(bf, &Ws[(wn + nt * 8 + lb8) * 20 + ch * 8 + lbc]);
                mma_f16(c[0][nt], af[0], bf);
                mma_f16(c[1][nt], af[1], bf);
            }
        }
    }

#pragma unroll
    for (int mt = 0; mt < 2; mt++) {
#pragma unroll
        for (int rr = 0; rr < 2; rr++) {
            const int m = bm + wm + mt * 16 + g + rr * 8;
            const int b = m >> 11, sIdx = m & (NS - 1);
#pragma unroll
            for (int nt = 0; nt < 8; nt++) {
                const int col = bn + wn + nt * 8 + 2 * t;
                const float vx = c[mt][nt][rr * 2 + 0] + bias[col];
                const float vy = c[mt][nt][rr * 2 + 1] + bias[col + 1];
                const int h = col >> 6, dh = col & 63;
                if (z != 2) {
                    *(uint32_t*)&out[((size_t)(b * NH + h) * NS + sIdx) * NDH + dh] =
                        f2h2(vx, vy);
                } else {
                    __half* o = out + ((size_t)(b * NH + h) * NDH) * NS;
                    o[(size_t)dh * NS + sIdx]       = __float2half_rn(vx);
                    o[(size_t)(dh + 1) * NS + sIdx] = __float2half_rn(vy);
                }
            }
        }
    }
}

// ---------------------------------------------------------------------------
// Output projection GEMM (ldmatrix): f32 row-major out.
// ---------------------------------------------------------------------------
__global__ __launch_bounds__(256) void gemm_out(
    const float* __restrict__ A, const float* __restrict__ W,
    const float* __restrict__ bias, float* __restrict__ out)
{
    __shared__ uint32_t As[128 * 20];
    __shared__ uint32_t Ws[128 * 20];

    const int tid = threadIdx.x;
    const int wid = tid >> 5, lane = tid & 31;
    const int g = lane >> 2, t = lane & 3;
    const int wm = (wid & 3) * 32;
    const int wn = (wid >> 2) * 64;
    const int bm = blockIdx.y * 128, bn = blockIdx.x * 128;

    const int lr = tid >> 1;
    const int lp = (tid & 1) * 8;

    const int la16 = lane & 15;
    const int lac  = (lane >> 4) * 4;
    const int lb8  = lane & 7;
    const int lbc  = ((lane >> 3) & 1) * 4;

    float c[2][8][4];
#pragma unroll
    for (int i = 0; i < 2; i++)
#pragma unroll
        for (int j = 0; j < 8; j++)
#pragma unroll
            for (int q = 0; q < 4; q++) c[i][j][q] = 0.f;

    const float* aptr = A + (size_t)(bm + lr) * ND + lp * 2;
    const float* wptr = W + (size_t)(bn + lr) * ND + lp * 2;

    for (int k0 = 0; k0 < ND; k0 += 32) {
        float4 a0 = *(const float4*)(aptr + k0);
        float4 a1 = *(const float4*)(aptr + k0 + 4);
        float4 a2 = *(const float4*)(aptr + k0 + 8);
        float4 a3 = *(const float4*)(aptr + k0 + 12);
        float4 w0 = *(const float4*)(wptr + k0);
        float4 w1 = *(const float4*)(wptr + k0 + 4);
        float4 w2 = *(const float4*)(wptr + k0 + 8);
        float4 w3 = *(const float4*)(wptr + k0 + 12);
        __syncthreads();
        *(uint4*)&As[lr * 20 + lp] =
            make_uint4(f2h2(a0.x, a0.y), f2h2(a0.z, a0.w), f2h2(a1.x, a1.y), f2h2(a1.z, a1.w));
        *(uint4*)&As[lr * 20 + lp + 4] =
            make_uint4(f2h2(a2.x, a2.y), f2h2(a2.z, a2.w), f2h2(a3.x, a3.y), f2h2(a3.z, a3.w));
        *(uint4*)&Ws[lr * 20 + lp] =
            make_uint4(f2h2(w0.x, w0.y), f2h2(w0.z, w0.w), f2h2(w1.x, w1.y), f2h2(w1.z, w1.w));
        *(uint4*)&Ws[lr * 20 + lp + 4] =
            make_uint4(f2h2(w2.x, w2.y), f2h2(w2.z, w2.w), f2h2(w3.x, w3.y), f2h2(w3.z, w3.w));
        __syncthreads();

#pragma unroll
        for (int ch = 0; ch < 2; ch++) {
            uint32_t af[2][4];
            ldm_x4(af[0], &As[(wm + la16)      * 20 + ch * 8 + lac]);
            ldm_x4(af[1], &As[(wm + 16 + la16) * 20 + ch * 8 + lac]);
#pragma unroll
            for (int nt = 0; nt < 8; nt++) {
                uint32_t bf[2];
                ldm_x2(bf, &Ws[(wn + nt * 8 + lb8) * 20 + ch * 8 + lbc]);
                mma_f16(c[0][nt], af[0], bf);
                mma_f16(c[1][nt], af[1], bf);
            }
        }
    }

#pragma unroll
    for (int mt = 0; mt < 2; mt++) {
#pragma unroll
        for (int rr = 0; rr < 2; rr++) {
            const int m = bm + wm + mt * 16 + g + rr * 8;
#pragma unroll
            for (int nt = 0; nt < 8; nt++) {
                const int col = bn + wn + nt * 8 + 2 * t;
                *(float2*)&out[(size_t)m * ND + col] = make_float2(
                    c[mt][nt][rr * 2 + 0] + bias[col],
                    c[mt][nt][rr * 2 + 1] + bias[col + 1]);
            }
        }
    }
}

// ---------------------------------------------------------------------------
// Attention v7 (measured best: 298 us): fp16 m16n8k16, scalar fragment LDS,
// cp.async double-buffered K/V, separate E buffer, 3 syncs/tile.
// Block = 64 q rows, 256 threads (8 warps: 4m x 2n). Warp tile 16q x 32k.
// ---------------------------------------------------------------------------
#define NT_TILES (NS / 64)
#define KST 36
__global__ __launch_bounds__(256) void attn_f16(
    const int* __restrict__ mask, float* __restrict__ wout)
{
    extern __shared__ uint32_t dsm[];
    uint32_t* KsB = dsm;                       // 2 x 64*36
    uint32_t* VsB = dsm + 2 * 64 * KST;        // 2 x 64*36
    uint32_t* Es  = VsB + 2 * 64 * KST;        // 64*36
    float*    red = (float*)(Es + 64 * KST);   // 128 floats

    const int b = blockIdx.z, h = blockIdx.y;
    const int q0 = blockIdx.x * 64;
    const int tid = threadIdx.x;
    const int wid = tid >> 5, lane = tid & 31;
    const int g = lane >> 2, t = lane & 3;
    const int wm = (wid & 3) * 16;
    const int wn = (wid >> 2) * 32;
    const size_t bh = (size_t)(b * NH + h);

    const int sr = tid >> 2;
    const int sch = tid & 3;

    // Stage Q (half, 64x64) into Es
    const __half* qptr = g_q + (bh * NS + q0) * NDH;
    cpa16(&Es[sr * KST + sch * 4],      qptr + sr * NDH + sch * 8);
    cpa16(&Es[sr * KST + sch * 4 + 16], qptr + sr * NDH + sch * 8 + 32);
    cpa_commit();
    cpa_wait0();
    __syncthreads();

    uint32_t qf[4][4];
#pragma unroll
    for (int ch = 0; ch < 4; ch++) {
        qf[ch][0] = Es[(wm + g)     * KST + ch * 8 + t];
        qf[ch][1] = Es[(wm + g + 8) * KST + ch * 8 + t];
        qf[ch][2] = Es[(wm + g)     * KST + ch * 8 + t + 4];
        qf[ch][3] = Es[(wm + g + 8) * KST + ch * 8 + t + 4];
    }
    __syncthreads();

    float cacc[4][4];
#pragma unroll
    for (int nt = 0; nt < 4; nt++)
#pragma unroll
        for (int q = 0; q < 4; q++) cacc[nt][q] = 0.f;
    float rs0 = 0.f, rs1 = 0.f;

    const int* mbase = mask + (size_t)b * NS * NS;
    float* wbase = wout ? wout + bh * NS * NS : nullptr;
    const __half* kbase = g_k + bh * NS * NDH;
    const __half* vbase = g_v + bh * (size_t)NDH * NS;

    cpa16(&KsB[sr * KST + sch * 4],      kbase + sr * NDH + sch * 8);
    cpa16(&KsB[sr * KST + sch * 4 + 16], kbase + sr * NDH + sch * 8 + 32);
    cpa16(&VsB[sr * KST + sch * 4],      vbase + (size_t)sr * NS + sch * 8);
    cpa16(&VsB[sr * KST + sch * 4 + 16], vbase + (size_t)sr * NS + sch * 8 + 32);
    cpa_commit();

    for (int kt = 0; kt < NT_TILES; kt++) {
        if (kt + 1 < NT_TILES) {
            const int nb = (kt + 1) & 1;
            const __half* kp = kbase + (size_t)(kt + 1) * 64 * NDH;
            const __half* vp = vbase + (size_t)(kt + 1) * 64;
            uint32_t* kd = KsB + nb * 64 * KST;
            uint32_t* vd = VsB + nb * 64 * KST;
            cpa16(&kd[sr * KST + sch * 4],      kp + sr * NDH + sch * 8);
            cpa16(&kd[sr * KST + sch * 4 + 16], kp + sr * NDH + sch * 8 + 32);
            cpa16(&vd[sr * KST + sch * 4],      vp + (size_t)sr * NS + sch * 8);
            cpa16(&vd[sr * KST + sch * 4 + 16], vp + (size_t)sr * NS + sch * 8 + 32);
            cpa_commit();
            cpa_wait1();
        } else {
            cpa_wait0();
        }
        __syncthreads();

        const uint32_t* Ks = KsB + (kt & 1) * 64 * KST;
        const uint32_t* Vs = VsB + (kt & 1) * 64 * KST;

        float lg[4][4];
#pragma unroll
        for (int nt = 0; nt < 4; nt++)
#pragma unroll
            for (int q = 0; q < 4; q++) lg[nt][q] = 0.f;
#pragma unroll
        for (int ch = 0; ch < 4; ch++) {
#pragma unroll
            for (int nt = 0; nt < 4; nt++) {
                const int kc = wn + nt * 8;
                uint32_t bf[2];
                bf[0] = Ks[(kc + g) * KST + ch * 8 + t];
                bf[1] = Ks[(kc + g) * KST + ch * 8 + t + 4];
                mma_f16(lg[nt], qf[ch], bf);
            }
        }

        const int qr0 = q0 + wm + g, qr1 = qr0 + 8;
#pragma unroll
        for (int nt = 0; nt < 4; nt++) {
            const int klocal = wn + nt * 8 + 2 * t;
            const int kcg = kt * 64 + klocal;
            int2 m0 = *(const int2*)(mbase + (size_t)qr0 * NS + kcg);
            int2 m1 = *(const int2*)(mbase + (size_t)qr1 * NS + kcg);
            float e0 = m0.x ? 0.f : __expf(lg[nt][0] * 0.125f);
            float e1 = m0.y ? 0.f : __expf(lg[nt][1] * 0.125f);
            float e2 = m1.x ? 0.f : __expf(lg[nt][2] * 0.125f);
            float e3 = m1.y ? 0.f : __expf(lg[nt][3] * 0.125f);
            rs0 += e0 + e1;
            rs1 += e2 + e3;
            if (wbase) {
                *(float2*)&wbase[(size_t)qr0 * NS + kcg] = make_float2(e0, e1);
                *(float2*)&wbase[(size_t)qr1 * NS + kcg] = make_float2(e2, e3);
            }
            const int pair = (klocal >> 1);
            Es[(wm + g)     * KST + pair] = f2h2(e0, e1);
            Es[(wm + g + 8) * KST + pair] = f2h2(e2, e3);
        }
        __syncthreads();

#pragma unroll
        for (int ch = 0; ch < 4; ch++) {
            uint32_t af[4];
            af[0] = Es[(wm + g)     * KST + ch * 8 + t];
            af[1] = Es[(wm + g + 8) * KST + ch * 8 + t];
            af[2] = Es[(wm + g)     * KST + ch * 8 + t + 4];
            af[3] = Es[(wm + g + 8) * KST + ch * 8 + t + 4];
#pragma unroll
            for (int nt = 0; nt < 4; nt++) {
                const int dc = wn + nt * 8 + g;
                uint32_t bf[2];
                bf[0] = Vs[dc * KST + ch * 8 + t];
                bf[1] = Vs[dc * KST + ch * 8 + t + 4];
                mma_f16(cacc[nt], af, bf);
            }
        }
        __syncthreads();
    }

    rs0 += __shfl_xor_sync(0xffffffffu, rs0, 1);
    rs0 += __shfl_xor_sync(0xffffffffu, rs0, 2);
    rs1 += __shfl_xor_sync(0xffffffffu, rs1, 1);
    rs1 += __shfl_xor_sync(0xffffffffu, rs1, 2);
    if (t == 0) {
        const int half = (wid >= 4) ? 64 : 0;
        red[half + wm + g]     = rs0;
        red[half + wm + g + 8] = rs1;
    }
    __syncthreads();
    const float tot0 = red[wm + g]     + red[64 + wm + g];
    const float tot1 = red[wm + g + 8] + red[64 + wm + g + 8];
    if (wid < 4 && t == 0) {
        g_rowsum[bh * NS + q0 + wm + g]     = tot0;
        g_rowsum[bh * NS + q0 + wm + g + 8] = tot1;
    }
    const float inv0 = 1.f / tot0, inv1 = 1.f / tot1;

    const int q = q0 + wm + g;
#pragma unroll
    for (int nt = 0; nt < 4; nt++) {
        const int dh = wn + nt * 8 + 2 * t;
        *(float2*)&g_attn[((size_t)b * NS + q) * ND + h * NDH + dh] =
            make_float2(cacc[nt][0] * inv0, cacc[nt][1] * inv0);
        *(float2*)&g_attn[((size_t)b * NS + q + 8) * ND + h * NDH + dh] =
            make_float2(cacc[nt][2] * inv1, cacc[nt][3] * inv1);
    }
}

// Scale each weights row by 1/rowsum (DRAM-roofline streaming kernel)
__global__ __launch_bounds__(128) void norm_w(float* __restrict__ w)
{
    const int row = blockIdx.x;
    const float inv = 1.f / g_rowsum[row];
    float4* p = (float4*)(w + (size_t)row * NS);
#pragma unroll
    for (int i = threadIdx.x; i < NS / 4; i += 128) {
        float4 v = p[i];
        v.x *= inv; v.y *= inv; v.z *= inv; v.w *= inv;
        p[i] = v;
    }
}

extern "C" void kernel_launch(void* const* d_in, const int* in_sizes, int n_in,
                              void* d_out, int out_size)
{
    const float* Xq  = (const float*)d_in[0];
    const float* Xk  = (const float*)d_in[1];
    const float* Xv  = (const float*)d_in[2];
    const int*   msk = (const int*)d_in[3];
    const float* Wq  = (const float*)d_in[4];
    const float* bq  = (const float*)d_in[5];
    const float* Wk  = (const float*)d_in[6];
    const float* bk  = (const float*)d_in[7];
    const float* Wv  = (const float*)d_in[8];
    const float* bv  = (const float*)d_in[9];
    const float* Wo  = (const float*)d_in[10];
    const float* bo  = (const float*)d_in[11];

    float* out = (float*)d_out;
    const size_t n_attn = (size_t)NB * NS * ND;
    const size_t n_w    = (size_t)NB * NH * NS * NS;

    float* attn_dst = nullptr;
    float* w_dst = nullptr;
    if ((size_t)out_size >= n_attn + n_w) { attn_dst = out; w_dst = out + n_attn; }
    else if ((size_t)out_size >= n_w)     { w_dst = out; }
    else                                  { attn_dst = out; }

    __half *pq, *pk, *pv;
    float *pa;
    cudaGetSymbolAddress((void**)&pq, g_q);
    cudaGetSymbolAddress((void**)&pk, g_k);
    cudaGetSymbolAddress((void**)&pv, g_v);
    cudaGetSymbolAddress((void**)&pa, g_attn);

    // Batched Q/K/V projections: one launch, 3 problems via grid.z
    P3 p;
    p.A[0] = Xq; p.W[0] = Wq; p.B[0] = bq; p.O[0] = pq;
    p.A[1] = Xk; p.W[1] = Wk; p.B[1] = bk; p.O[1] = pk;
    p.A[2] = Xv; p.W[2] = Wv; p.B[2] = bv; p.O[2] = pv;
    gemm_qkv<<<dim3(ND / 128, NM / 128, 3), 256>>>(p);

    const int attn_smem = (5 * 64 * KST) * 4 + 128 * 4 + 256;  // ~46.8 KB
    cudaFuncSetAttribute(attn_f16, cudaFuncAttributeMaxDynamicSharedMemorySize, attn_smem);
    attn_f16<<<dim3(NS / 64, NH, NB), 256, attn_smem>>>(msk, w_dst);

    // norm_w (DRAM-bound) and output projection (compute-bound) are
    // independent: run them concurrently via a forked stream so their
    // resource use overlaps. Standard cross-stream event pattern, legal
    // under graph capture.
    dim3 ggrid(ND / 128, NM / 128);
    if (w_dst && attn_dst) {
        cudaStream_t s2;
        cudaStreamCreateWithFlags(&s2, cudaStreamNonBlocking);
        cudaEvent_t e1, e2;
        cudaEventCreateWithFlags(&e1, cudaEventDisableTiming);
        cudaEventCreateWithFlags(&e2, cudaEventDisableTiming);
        cudaEventRecord(e1, 0);
        cudaStreamWaitEvent(s2, e1, 0);
        norm_w<<<NB * NH * NS, 128, 0, s2>>>(w_dst);
        gemm_out<<<ggrid, 256>>>(pa, Wo, bo, attn_dst);
        cudaEventRecord(e2, s2);
        cudaStreamWaitEvent(0, e2, 0);
    } else {
        if (w_dst) norm_w<<<NB * NH * NS, 128>>>(w_dst);
        if (attn_dst) gemm_out<<<ggrid, 256>>>(pa, Wo, bo, attn_dst);
    }
}

// round 11
// speedup vs baseline: 1.3761x; 1.1568x over previous
#include <cuda_runtime.h>
#include <cuda_fp16.h>
#include <cstdint>

// Problem constants
#define NB 2
#define NS 2048
#define ND 1024
#define NH 16
#define NDH 64
#define NM (NB * NS)

// Scratch (device globals: allocation-free)
__device__ __half g_xh[3][(size_t)NM * ND];            // fp16 copies of Xq,Xk,Xv
__device__ __half g_wh[4][(size_t)ND * ND];            // fp16 copies of Wq,Wk,Wv,Wo
__device__ __half g_q[(size_t)NB * NH * NS * NDH];     // [b,h,s,dh]
__device__ __half g_k[(size_t)NB * NH * NS * NDH];     // [b,h,s,dh]
__device__ __half g_v[(size_t)NB * NH * NS * NDH];     // [b,h,dh,s]  TRANSPOSED
__device__ __half g_attn[(size_t)NB * NS * ND];        // fp16 concat output
__device__ float  g_rowsum[(size_t)NB * NH * NS];

// ---------------- helpers ----------------
__device__ __forceinline__ uint32_t f2h2(float a, float b) {
    __half2 h = __floats2half2_rn(a, b);
    return *reinterpret_cast<uint32_t*>(&h);
}

__device__ __forceinline__ void mma_f16(float c[4], const uint32_t a[4], const uint32_t b[2]) {
    asm volatile(
        "mma.sync.aligned.m16n8k16.row.col.f32.f16.f16.f32 "
        "{%0,%1,%2,%3}, {%4,%5,%6,%7}, {%8,%9}, {%0,%1,%2,%3};"
        : "+f"(c[0]), "+f"(c[1]), "+f"(c[2]), "+f"(c[3])
        : "r"(a[0]), "r"(a[1]), "r"(a[2]), "r"(a[3]), "r"(b[0]), "r"(b[1]));
}

__device__ __forceinline__ void ldm_x4(uint32_t* r, const uint32_t* p) {
    uint32_t a = (uint32_t)__cvta_generic_to_shared(p);
    asm volatile("ldmatrix.sync.aligned.m8n8.x4.shared.b16 {%0,%1,%2,%3}, [%4];"
        : "=r"(r[0]), "=r"(r[1]), "=r"(r[2]), "=r"(r[3]) : "r"(a));
}
__device__ __forceinline__ void ldm_x2(uint32_t* r, const uint32_t* p) {
    uint32_t a = (uint32_t)__cvta_generic_to_shared(p);
    asm volatile("ldmatrix.sync.aligned.m8n8.x2.shared.b16 {%0,%1}, [%2];"
        : "=r"(r[0]), "=r"(r[1]) : "r"(a));
}

__device__ __forceinline__ void cpa16(void* smem, const void* g) {
    uint32_t s = (uint32_t)__cvta_generic_to_shared(smem);
    asm volatile("cp.async.cg.shared.global [%0], [%1], 16;" :: "r"(s), "l"(g));
}
__device__ __forceinline__ void cpa_commit() { asm volatile("cp.async.commit_group;"); }
__device__ __forceinline__ void cpa_wait0() { asm volatile("cp.async.wait_group 0;" ::: "memory"); }
__device__ __forceinline__ void cpa_wait1() { asm volatile("cp.async.wait_group 1;" ::: "memory"); }

// ---------------------------------------------------------------------------
// Batched f32 -> f16 conversion (DRAM-bound, ~15 us for 84 MB)
// ---------------------------------------------------------------------------
struct CvtArgs {
    const float* s[7];
    __half* d[7];
    int n4[7];   // element count / 4
};

__global__ __launch_bounds__(256) void cvt_f2h(CvtArgs a)
{
    const int z = blockIdx.y;
    const float4* s = (const float4*)a.s[z];
    __half* d = a.d[z];
    const int n4 = a.n4[z];
    for (int i = blockIdx.x * blockDim.x + threadIdx.x; i < n4;
         i += gridDim.x * blockDim.x) {
        float4 f = s[i];
        *(uint2*)(d + (size_t)i * 4) = make_uint2(f2h2(f.x, f.y), f2h2(f.z, f.w));
    }
}

// ---------------------------------------------------------------------------
// fp16-input GEMM with cp.async double-buffered staging.
// C = A(f16, MxK) @ W^T(f16, NxK) + bias(f32). BM=BN=128, BK=32, 256 thr.
// Fragments via ldmatrix. Smem row = 16 words (BK=32 halves) + 4 pad.
// Staging: 128 rows x 4 chunks(16B) per operand; thread does 2 chunks each.
// ---------------------------------------------------------------------------
#define HG_ISSUE(buf, k0)                                                      \
    do {                                                                       \
        cpa16(&As[buf][sr0 * 20 + sch * 4], abase + (size_t)sr0 * ND + (k0) + sch * 8); \
        cpa16(&As[buf][sr1 * 20 + sch * 4], abase + (size_t)sr1 * ND + (k0) + sch * 8); \
        cpa16(&Ws[buf][sr0 * 20 + sch * 4], wbase + (size_t)sr0 * ND + (k0) + sch * 8); \
        cpa16(&Ws[buf][sr1 * 20 + sch * 4], wbase + (size_t)sr1 * ND + (k0) + sch * 8); \
        cpa_commit();                                                          \
    } while (0)

template <int MODE>   // 0: f32 row-major; 1: half [b,h,s,dh]; 2: half [b,h,dh,s]
__device__ __forceinline__ void hgemm_body(
    const __half* __restrict__ A, const __half* __restrict__ W,
    const float* __restrict__ bias, void* __restrict__ outv,
    int bm, int bn)
{
    __shared__ uint32_t As[2][128 * 20];
    __shared__ uint32_t Ws[2][128 * 20];

    const int tid = threadIdx.x;
    const int wid = tid >> 5, lane = tid & 31;
    const int g = lane >> 2, t = lane & 3;
    const int wm = (wid & 3) * 32;
    const int wn = (wid >> 2) * 64;

    const int sr0 = tid >> 2, sr1 = sr0 + 64;   // staging rows
    const int sch = tid & 3;                    // staging chunk

    const int la16 = lane & 15;
    const int lac  = (lane >> 4) * 4;
    const int lb8  = lane & 7;
    const int lbc  = ((lane >> 3) & 1) * 4;

    float c[2][8][4];
#pragma unroll
    for (int i = 0; i < 2; i++)
#pragma unroll
        for (int j = 0; j < 8; j++)
#pragma unroll
            for (int q = 0; q < 4; q++) c[i][j][q] = 0.f;

    const __half* abase = A + (size_t)bm * ND;
    const __half* wbase = W + (size_t)bn * ND;

    HG_ISSUE(0, 0);

    for (int k0 = 0; k0 < ND; k0 += 32) {
        const int cur = (k0 >> 5) & 1;
        if (k0 + 32 < ND) {
            HG_ISSUE(cur ^ 1, k0 + 32);
            cpa_wait1();
        } else {
            cpa_wait0();
        }
        __syncthreads();

#pragma unroll
        for (int ch = 0; ch < 2; ch++) {
            uint32_t af[2][4];
            ldm_x4(af[0], &As[cur][(wm + la16)      * 20 + ch * 8 + lac]);
            ldm_x4(af[1], &As[cur][(wm + 16 + la16) * 20 + ch * 8 + lac]);
#pragma unroll
            for (int nt = 0; nt < 8; nt++) {
                uint32_t bf[2];
                ldm_x2(bf, &Ws[cur][(wn + nt * 8 + lb8) * 20 + ch * 8 + lbc]);
                mma_f16(c[0][nt], af[0], bf);
                mma_f16(c[1][nt], af[1], bf);
            }
        }
        __syncthreads();   // all warps done with cur before it is re-filled
    }

#pragma unroll
    for (int mt = 0; mt < 2; mt++) {
#pragma unroll
        for (int rr = 0; rr < 2; rr++) {
            const int m = bm + wm + mt * 16 + g + rr * 8;
            const int b = m >> 11, sIdx = m & (NS - 1);
#pragma unroll
            for (int nt = 0; nt < 8; nt++) {
                const int col = bn + wn + nt * 8 + 2 * t;
                const float vx = c[mt][nt][rr * 2 + 0] + bias[col];
                const float vy = c[mt][nt][rr * 2 + 1] + bias[col + 1];
                if (MODE == 0) {
                    *(float2*)&((float*)outv)[(size_t)m * ND + col] = make_float2(vx, vy);
                } else if (MODE == 1) {
                    const int h = col >> 6, dh = col & 63;
                    *(uint32_t*)&((__half*)outv)[((size_t)(b * NH + h) * NS + sIdx) * NDH + dh] =
                        f2h2(vx, vy);
                } else {
                    const int h = col >> 6, dh = col & 63;
                    __half* o = (__half*)outv + ((size_t)(b * NH + h) * NDH) * NS;
                    o[(size_t)dh * NS + sIdx]       = __float2half_rn(vx);
                    o[(size_t)(dh + 1) * NS + sIdx] = __float2half_rn(vy);
                }
            }
        }
    }
}

// Batched QKV projection: grid.z = 0(Q),1(K) -> [b,h,s,dh]; 2(V) -> [b,h,dh,s]
struct P3h {
    const __half* A[3];
    const __half* W[3];
    const float* B[3];
    __half* O[3];
};

__global__ __launch_bounds__(256) void gemm_qkv(P3h p)
{
    const int z = blockIdx.z;
    if (z != 2)
        hgemm_body<1>(p.A[z], p.W[z], p.B[z], p.O[z], blockIdx.y * 128, blockIdx.x * 128);
    else
        hgemm_body<2>(p.A[z], p.W[z], p.B[z], p.O[z], blockIdx.y * 128, blockIdx.x * 128);
}

__global__ __launch_bounds__(256) void gemm_out(
    const __half* __restrict__ A, const __half* __restrict__ W,
    const float* __restrict__ bias, float* __restrict__ out)
{
    hgemm_body<0>(A, W, bias, out, blockIdx.y * 128, blockIdx.x * 128);
}

// ---------------------------------------------------------------------------
// Attention v7 (measured best): fp16 m16n8k16, scalar fragment LDS,
// cp.async double-buffered K/V, separate E buffer, 3 syncs/tile.
// Epilogue now writes g_attn in fp16 (identical rounding to previous
// gemm_out staging conversion).
// ---------------------------------------------------------------------------
#define NT_TILES (NS / 64)
#define KST 36
__global__ __launch_bounds__(256) void attn_f16(
    const int* __restrict__ mask, float* __restrict__ wout)
{
    extern __shared__ uint32_t dsm[];
    uint32_t* KsB = dsm;                       // 2 x 64*36
    uint32_t* VsB = dsm + 2 * 64 * KST;        // 2 x 64*36
    uint32_t* Es  = VsB + 2 * 64 * KST;        // 64*36
    float*    red = (float*)(Es + 64 * KST);   // 128 floats

    const int b = blockIdx.z, h = blockIdx.y;
    const int q0 = blockIdx.x * 64;
    const int tid = threadIdx.x;
    const int wid = tid >> 5, lane = tid & 31;
    const int g = lane >> 2, t = lane & 3;
    const int wm = (wid & 3) * 16;
    const int wn = (wid >> 2) * 32;
    const size_t bh = (size_t)(b * NH + h);

    const int sr = tid >> 2;
    const int sch = tid & 3;

    const __half* qptr = g_q + (bh * NS + q0) * NDH;
    cpa16(&Es[sr * KST + sch * 4],      qptr + sr * NDH + sch * 8);
    cpa16(&Es[sr * KST + sch * 4 + 16], qptr + sr * NDH + sch * 8 + 32);
    cpa_commit();
    cpa_wait0();
    __syncthreads();

    uint32_t qf[4][4];
#pragma unroll
    for (int ch = 0; ch < 4; ch++) {
        qf[ch][0] = Es[(wm + g)     * KST + ch * 8 + t];
        qf[ch][1] = Es[(wm + g + 8) * KST + ch * 8 + t];
        qf[ch][2] = Es[(wm + g)     * KST + ch * 8 + t + 4];
        qf[ch][3] = Es[(wm + g + 8) * KST + ch * 8 + t + 4];
    }
    __syncthreads();

    float cacc[4][4];
#pragma unroll
    for (int nt = 0; nt < 4; nt++)
#pragma unroll
        for (int q = 0; q < 4; q++) cacc[nt][q] = 0.f;
    float rs0 = 0.f, rs1 = 0.f;

    const int* mbase = mask + (size_t)b * NS * NS;
    float* wbase = wout ? wout + bh * NS * NS : nullptr;
    const __half* kbase = g_k + bh * NS * NDH;
    const __half* vbase = g_v + bh * (size_t)NDH * NS;

    cpa16(&KsB[sr * KST + sch * 4],      kbase + sr * NDH + sch * 8);
    cpa16(&KsB[sr * KST + sch * 4 + 16], kbase + sr * NDH + sch * 8 + 32);
    cpa16(&VsB[sr * KST + sch * 4],      vbase + (size_t)sr * NS + sch * 8);
    cpa16(&VsB[sr * KST + sch * 4 + 16], vbase + (size_t)sr * NS + sch * 8 + 32);
    cpa_commit();

    for (int kt = 0; kt < NT_TILES; kt++) {
        if (kt + 1 < NT_TILES) {
            const int nb = (kt + 1) & 1;
            const __half* kp = kbase + (size_t)(kt + 1) * 64 * NDH;
            const __half* vp = vbase + (size_t)(kt + 1) * 64;
            uint32_t* kd = KsB + nb * 64 * KST;
            uint32_t* vd = VsB + nb * 64 * KST;
            cpa16(&kd[sr * KST + sch * 4],      kp + sr * NDH + sch * 8);
            cpa16(&kd[sr * KST + sch * 4 + 16], kp + sr * NDH + sch * 8 + 32);
            cpa16(&vd[sr * KST + sch * 4],      vp + (size_t)sr * NS + sch * 8);
            cpa16(&vd[sr * KST + sch * 4 + 16], vp + (size_t)sr * NS + sch * 8 + 32);
            cpa_commit();
            cpa_wait1();
        } else {
            cpa_wait0();
        }
        __syncthreads();

        const uint32_t* Ks = KsB + (kt & 1) * 64 * KST;
        const uint32_t* Vs = VsB + (kt & 1) * 64 * KST;

        float lg[4][4];
#pragma unroll
        for (int nt = 0; nt < 4; nt++)
#pragma unroll
            for (int q = 0; q < 4; q++) lg[nt][q] = 0.f;
#pragma unroll
        for (int ch = 0; ch < 4; ch++) {
#pragma unroll
            for (int nt = 0; nt < 4; nt++) {
                const int kc = wn + nt * 8;
                uint32_t bf[2];
                bf[0] = Ks[(kc + g) * KST + ch * 8 + t];
                bf[1] = Ks[(kc + g) * KST + ch * 8 + t + 4];
                mma_f16(lg[nt], qf[ch], bf);
            }
        }

        const int qr0 = q0 + wm + g, qr1 = qr0 + 8;
#pragma unroll
        for (int nt = 0; nt < 4; nt++) {
            const int klocal = wn + nt * 8 + 2 * t;
            const int kcg = kt * 64 + klocal;
            int2 m0 = *(const int2*)(mbase + (size_t)qr0 * NS + kcg);
            int2 m1 = *(const int2*)(mbase + (size_t)qr1 * NS + kcg);
            float e0 = m0.x ? 0.f : __expf(lg[nt][0] * 0.125f);
            float e1 = m0.y ? 0.f : __expf(lg[nt][1] * 0.125f);
            float e2 = m1.x ? 0.f : __expf(lg[nt][2] * 0.125f);
            float e3 = m1.y ? 0.f : __expf(lg[nt][3] * 0.125f);
            rs0 += e0 + e1;
            rs1 += e2 + e3;
            if (wbase) {
                *(float2*)&wbase[(size_t)qr0 * NS + kcg] = make_float2(e0, e1);
                *(float2*)&wbase[(size_t)qr1 * NS + kcg] = make_float2(e2, e3);
            }
            const int pair = (klocal >> 1);
            Es[(wm + g)     * KST + pair] = f2h2(e0, e1);
            Es[(wm + g + 8) * KST + pair] = f2h2(e2, e3);
        }
        __syncthreads();

#pragma unroll
        for (int ch = 0; ch < 4; ch++) {
            uint32_t af[4];
            af[0] = Es[(wm + g)     * KST + ch * 8 + t];
            af[1] = Es[(wm + g + 8) * KST + ch * 8 + t];
            af[2] = Es[(wm + g)     * KST + ch * 8 + t + 4];
            af[3] = Es[(wm + g + 8) * KST + ch * 8 + t + 4];
#pragma unroll
            for (int nt = 0; nt < 4; nt++) {
                const int dc = wn + nt * 8 + g;
                uint32_t bf[2];
                bf[0] = Vs[dc * KST + ch * 8 + t];
                bf[1] = Vs[dc * KST + ch * 8 + t + 4];
                mma_f16(cacc[nt], af, bf);
            }
        }
        __syncthreads();
    }

    rs0 += __shfl_xor_sync(0xffffffffu, rs0, 1);
    rs0 += __shfl_xor_sync(0xffffffffu, rs0, 2);
    rs1 += __shfl_xor_sync(0xffffffffu, rs1, 1);
    rs1 += __shfl_xor_sync(0xffffffffu, rs1, 2);
    if (t == 0) {
        const int half = (wid >= 4) ? 64 : 0;
        red[half + wm + g]     = rs0;
        red[half + wm + g + 8] = rs1;
    }
    __syncthreads();
    const float tot0 = red[wm + g]     + red[64 + wm + g];
    const float tot1 = red[wm + g + 8] + red[64 + wm + g + 8];
    if (wid < 4 && t == 0) {
        g_rowsum[bh * NS + q0 + wm + g]     = tot0;
        g_rowsum[bh * NS + q0 + wm + g + 8] = tot1;
    }
    const float inv0 = 1.f / tot0, inv1 = 1.f / tot1;

    // Normalized attn, concat layout, fp16 (same rounding as old staging cvt)
    const int q = q0 + wm + g;
#pragma unroll
    for (int nt = 0; nt < 4; nt++) {
        const int dh = wn + nt * 8 + 2 * t;
        *(uint32_t*)&g_attn[((size_t)b * NS + q) * ND + h * NDH + dh] =
            f2h2(cacc[nt][0] * inv0, cacc[nt][1] * inv0);
        *(uint32_t*)&g_attn[((size_t)b * NS + q + 8) * ND + h * NDH + dh] =
            f2h2(cacc[nt][2] * inv1, cacc[nt][3] * inv1);
    }
}

// Scale each weights row by 1/rowsum (DRAM-roofline streaming kernel)
__global__ __launch_bounds__(128) void norm_w(float* __restrict__ w)
{
    const int row = blockIdx.x;
    const float inv = 1.f / g_rowsum[row];
    float4* p = (float4*)(w + (size_t)row * NS);
#pragma unroll
    for (int i = threadIdx.x; i < NS / 4; i += 128) {
        float4 v = p[i];
        v.x *= inv; v.y *= inv; v.z *= inv; v.w *= inv;
        p[i] = v;
    }
}

extern "C" void kernel_launch(void* const* d_in, const int* in_sizes, int n_in,
                              void* d_out, int out_size)
{
    const float* Xq  = (const float*)d_in[0];
    const float* Xk  = (const float*)d_in[1];
    const float* Xv  = (const float*)d_in[2];
    const int*   msk = (const int*)d_in[3];
    const float* Wq  = (const float*)d_in[4];
    const float* bq  = (const float*)d_in[5];
    const float* Wk  = (const float*)d_in[6];
    const float* bk  = (const float*)d_in[7];
    const float* Wv  = (const float*)d_in[8];
    const float* bv  = (const float*)d_in[9];
    const float* Wo  = (const float*)d_in[10];
    const float* bo  = (const float*)d_in[11];

    float* out = (float*)d_out;
    const size_t n_attn = (size_t)NB * NS * ND;
    const size_t n_w    = (size_t)NB * NH * NS * NS;

    float* attn_dst = nullptr;
    float* w_dst = nullptr;
    if ((size_t)out_size >= n_attn + n_w) { attn_dst = out; w_dst = out + n_attn; }
    else if ((size_t)out_size >= n_w)     { w_dst = out; }
    else                                  { attn_dst = out; }

    __half *pxh, *pwh, *pq, *pk, *pv, *pa;
    cudaGetSymbolAddress((void**)&pxh, g_xh);
    cudaGetSymbolAddress((void**)&pwh, g_wh);
    cudaGetSymbolAddress((void**)&pq, g_q);
    cudaGetSymbolAddress((void**)&pk, g_k);
    cudaGetSymbolAddress((void**)&pv, g_v);
    cudaGetSymbolAddress((void**)&pa, g_attn);

    const size_t xN = (size_t)NM * ND;
    const size_t wN = (size_t)ND * ND;

    // 1) Convert inputs + weights to fp16 (one batched launch)
    CvtArgs ca;
    ca.s[0] = Xq; ca.d[0] = pxh + 0 * xN; ca.n4[0] = (int)(xN / 4);
    ca.s[1] = Xk; ca.d[1] = pxh + 1 * xN; ca.n4[1] = (int)(xN / 4);
    ca.s[2] = Xv; ca.d[2] = pxh + 2 * xN; ca.n4[2] = (int)(xN / 4);
    ca.s[3] = Wq; ca.d[3] = pwh + 0 * wN; ca.n4[3] = (int)(wN / 4);
    ca.s[4] = Wk; ca.d[4] = pwh + 1 * wN; ca.n4[4] = (int)(wN / 4);
    ca.s[5] = Wv; ca.d[5] = pwh + 2 * wN; ca.n4[5] = (int)(wN / 4);
    ca.s[6] = Wo; ca.d[6] = pwh + 3 * wN; ca.n4[6] = (int)(wN / 4);
    cvt_f2h<<<dim3(1024, 7), 256>>>(ca);

    // 2) Batched Q/K/V projections (fp16-in, cp.async pipelined)
    P3h p;
    p.A[0] = pxh + 0 * xN; p.W[0] = pwh + 0 * wN; p.B[0] = bq; p.O[0] = pq;
    p.A[1] = pxh + 1 * xN; p.W[1] = pwh + 1 * wN; p.B[1] = bk; p.O[1] = pk;
    p.A[2] = pxh + 2 * xN; p.W[2] = pwh + 2 * wN; p.B[2] = bv; p.O[2] = pv;
    gemm_qkv<<<dim3(ND / 128, NM / 128, 3), 256>>>(p);

    // 3) Attention
    const int attn_smem = (5 * 64 * KST) * 4 + 128 * 4 + 256;
    cudaFuncSetAttribute(attn_f16, cudaFuncAttributeMaxDynamicSharedMemorySize, attn_smem);
    attn_f16<<<dim3(NS / 64, NH, NB), 256, attn_smem>>>(msk, w_dst);

    // 4) norm_w (DRAM-bound) overlapped with output projection (compute-bound)
    dim3 ggrid(ND / 128, NM / 128);
    if (w_dst && attn_dst) {
        cudaStream_t s2;
        cudaStreamCreateWithFlags(&s2, cudaStreamNonBlocking);
        cudaEvent_t e1, e2;
        cudaEventCreateWithFlags(&e1, cudaEventDisableTiming);
        cudaEventCreateWithFlags(&e2, cudaEventDisableTiming);
        cudaEventRecord(e1, 0);
        cudaStreamWaitEvent(s2, e1, 0);
        norm_w<<<NB * NH * NS, 128, 0, s2>>>(w_dst);
        gemm_out<<<ggrid, 256>>>(pa, pwh + 3 * wN, bo, attn_dst);
        cudaEventRecord(e2, s2);
        cudaStreamWaitEvent(0, e2, 0);
    } else {
        if (w_dst) norm_w<<<NB * NH * NS, 128>>>(w_dst);
        if (attn_dst) gemm_out<<<ggrid, 256>>>(pa, pwh + 3 * wN, bo, attn_dst);
    }
}

// round 12
// speedup vs baseline: 1.4527x; 1.0557x over previous
#include <cuda_runtime.h>
#include <cuda_fp16.h>
#include <cstdint>

// Problem constants
#define NB 2
#define NS 2048
#define ND 1024
#define NH 16
#define NDH 64
#define NM (NB * NS)

// Scratch (device globals: allocation-free)
__device__ __half g_xh[3][(size_t)NM * ND];            // fp16 copies of Xq,Xk,Xv
__device__ __half g_wh[4][(size_t)ND * ND];            // fp16 copies of Wq,Wk,Wv,Wo
__device__ __half g_q[(size_t)NB * NH * NS * NDH];     // [b,h,s,dh]
__device__ __half g_k[(size_t)NB * NH * NS * NDH];     // [b,h,s,dh]
__device__ __half g_v[(size_t)NB * NH * NS * NDH];     // [b,h,dh,s]  TRANSPOSED
__device__ __half g_attn[(size_t)NB * NS * ND];        // fp16 concat output
__device__ __half g_ew[(size_t)NB * NH * NS * NS];     // fp16 unnormalized weights
__device__ float  g_rowsum[(size_t)NB * NH * NS];

// ---------------- helpers ----------------
__device__ __forceinline__ uint32_t f2h2(float a, float b) {
    __half2 h = __floats2half2_rn(a, b);
    return *reinterpret_cast<uint32_t*>(&h);
}

__device__ __forceinline__ void mma_f16(float c[4], const uint32_t a[4], const uint32_t b[2]) {
    asm volatile(
        "mma.sync.aligned.m16n8k16.row.col.f32.f16.f16.f32 "
        "{%0,%1,%2,%3}, {%4,%5,%6,%7}, {%8,%9}, {%0,%1,%2,%3};"
        : "+f"(c[0]), "+f"(c[1]), "+f"(c[2]), "+f"(c[3])
        : "r"(a[0]), "r"(a[1]), "r"(a[2]), "r"(a[3]), "r"(b[0]), "r"(b[1]));
}

__device__ __forceinline__ void ldm_x4(uint32_t* r, const uint32_t* p) {
    uint32_t a = (uint32_t)__cvta_generic_to_shared(p);
    asm volatile("ldmatrix.sync.aligned.m8n8.x4.shared.b16 {%0,%1,%2,%3}, [%4];"
        : "=r"(r[0]), "=r"(r[1]), "=r"(r[2]), "=r"(r[3]) : "r"(a));
}
__device__ __forceinline__ void ldm_x2(uint32_t* r, const uint32_t* p) {
    uint32_t a = (uint32_t)__cvta_generic_to_shared(p);
    asm volatile("ldmatrix.sync.aligned.m8n8.x2.shared.b16 {%0,%1}, [%2];"
        : "=r"(r[0]), "=r"(r[1]) : "r"(a));
}

__device__ __forceinline__ void cpa16(void* smem, const void* g) {
    uint32_t s = (uint32_t)__cvta_generic_to_shared(smem);
    asm volatile("cp.async.cg.shared.global [%0], [%1], 16;" :: "r"(s), "l"(g));
}
__device__ __forceinline__ void cpa_commit() { asm volatile("cp.async.commit_group;"); }
__device__ __forceinline__ void cpa_wait0() { asm volatile("cp.async.wait_group 0;" ::: "memory"); }
__device__ __forceinline__ void cpa_wait1() { asm volatile("cp.async.wait_group 1;" ::: "memory"); }

// ---------------------------------------------------------------------------
// Batched f32 -> f16 conversion
// ---------------------------------------------------------------------------
struct CvtArgs {
    const float* s[7];
    __half* d[7];
    int n4[7];
};

__global__ __launch_bounds__(256) void cvt_f2h(CvtArgs a)
{
    const int z = blockIdx.y;
    const float4* s = (const float4*)a.s[z];
    __half* d = a.d[z];
    const int n4 = a.n4[z];
    for (int i = blockIdx.x * blockDim.x + threadIdx.x; i < n4;
         i += gridDim.x * blockDim.x) {
        float4 f = s[i];
        *(uint2*)(d + (size_t)i * 4) = make_uint2(f2h2(f.x, f.y), f2h2(f.z, f.w));
    }
}

// ---------------------------------------------------------------------------
// fp16-input GEMM with cp.async double-buffered staging (round-11 version).
// ---------------------------------------------------------------------------
#define HG_ISSUE(buf, k0)                                                      \
    do {                                                                       \
        cpa16(&As[buf][sr0 * 20 + sch * 4], abase + (size_t)sr0 * ND + (k0) + sch * 8); \
        cpa16(&As[buf][sr1 * 20 + sch * 4], abase + (size_t)sr1 * ND + (k0) + sch * 8); \
        cpa16(&Ws[buf][sr0 * 20 + sch * 4], wbase + (size_t)sr0 * ND + (k0) + sch * 8); \
        cpa16(&Ws[buf][sr1 * 20 + sch * 4], wbase + (size_t)sr1 * ND + (k0) + sch * 8); \
        cpa_commit();                                                          \
    } while (0)

template <int MODE>   // 0: f32 row-major; 1: half [b,h,s,dh]; 2: half [b,h,dh,s]
__device__ __forceinline__ void hgemm_body(
    const __half* __restrict__ A, const __half* __restrict__ W,
    const float* __restrict__ bias, void* __restrict__ outv,
    int bm, int bn)
{
    __shared__ uint32_t As[2][128 * 20];
    __shared__ uint32_t Ws[2][128 * 20];

    const int tid = threadIdx.x;
    const int wid = tid >> 5, lane = tid & 31;
    const int g = lane >> 2, t = lane & 3;
    const int wm = (wid & 3) * 32;
    const int wn = (wid >> 2) * 64;

    const int sr0 = tid >> 2, sr1 = sr0 + 64;
    const int sch = tid & 3;

    const int la16 = lane & 15;
    const int lac  = (lane >> 4) * 4;
    const int lb8  = lane & 7;
    const int lbc  = ((lane >> 3) & 1) * 4;

    float c[2][8][4];
#pragma unroll
    for (int i = 0; i < 2; i++)
#pragma unroll
        for (int j = 0; j < 8; j++)
#pragma unroll
            for (int q = 0; q < 4; q++) c[i][j][q] = 0.f;

    const __half* abase = A + (size_t)bm * ND;
    const __half* wbase = W + (size_t)bn * ND;

    HG_ISSUE(0, 0);

    for (int k0 = 0; k0 < ND; k0 += 32) {
        const int cur = (k0 >> 5) & 1;
        if (k0 + 32 < ND) {
            HG_ISSUE(cur ^ 1, k0 + 32);
            cpa_wait1();
        } else {
            cpa_wait0();
        }
        __syncthreads();

#pragma unroll
        for (int ch = 0; ch < 2; ch++) {
            uint32_t af[2][4];
            ldm_x4(af[0], &As[cur][(wm + la16)      * 20 + ch * 8 + lac]);
            ldm_x4(af[1], &As[cur][(wm + 16 + la16) * 20 + ch * 8 + lac]);
#pragma unroll
            for (int nt = 0; nt < 8; nt++) {
                uint32_t bf[2];
                ldm_x2(bf, &Ws[cur][(wn + nt * 8 + lb8) * 20 + ch * 8 + lbc]);
                mma_f16(c[0][nt], af[0], bf);
                mma_f16(c[1][nt], af[1], bf);
            }
        }
        __syncthreads();
    }

#pragma unroll
    for (int mt = 0; mt < 2; mt++) {
#pragma unroll
        for (int rr = 0; rr < 2; rr++) {
            const int m = bm + wm + mt * 16 + g + rr * 8;
            const int b = m >> 11, sIdx = m & (NS - 1);
#pragma unroll
            for (int nt = 0; nt < 8; nt++) {
                const int col = bn + wn + nt * 8 + 2 * t;
                const float vx = c[mt][nt][rr * 2 + 0] + bias[col];
                const float vy = c[mt][nt][rr * 2 + 1] + bias[col + 1];
                if (MODE == 0) {
                    *(float2*)&((float*)outv)[(size_t)m * ND + col] = make_float2(vx, vy);
                } else if (MODE == 1) {
                    const int h = col >> 6, dh = col & 63;
                    *(uint32_t*)&((__half*)outv)[((size_t)(b * NH + h) * NS + sIdx) * NDH + dh] =
                        f2h2(vx, vy);
                } else {
                    const int h = col >> 6, dh = col & 63;
                    __half* o = (__half*)outv + ((size_t)(b * NH + h) * NDH) * NS;
                    o[(size_t)dh * NS + sIdx]       = __float2half_rn(vx);
                    o[(size_t)(dh + 1) * NS + sIdx] = __float2half_rn(vy);
                }
            }
        }
    }
}

struct P3h {
    const __half* A[3];
    const __half* W[3];
    const float* B[3];
    __half* O[3];
};

__global__ __launch_bounds__(256) void gemm_qkv(P3h p)
{
    const int z = blockIdx.z;
    if (z != 2)
        hgemm_body<1>(p.A[z], p.W[z], p.B[z], p.O[z], blockIdx.y * 128, blockIdx.x * 128);
    else
        hgemm_body<2>(p.A[z], p.W[z], p.B[z], p.O[z], blockIdx.y * 128, blockIdx.x * 128);
}

__global__ __launch_bounds__(256) void gemm_out(
    const __half* __restrict__ A, const __half* __restrict__ W,
    const float* __restrict__ bias, float* __restrict__ out)
{
    hgemm_body<0>(A, W, bias, out, blockIdx.y * 128, blockIdx.x * 128);
}

// ---------------------------------------------------------------------------
// Attention (v7 core). Weight store is now fp16 to g_ew — the SAME packed
// half2 value already produced for the PV smem buffer (zero extra math),
// halving attn's weight-store bytes.
// ---------------------------------------------------------------------------
#define NT_TILES (NS / 64)
#define KST 36
__global__ __launch_bounds__(256) void attn_f16(
    const int* __restrict__ mask, int store_w)
{
    extern __shared__ uint32_t dsm[];
    uint32_t* KsB = dsm;
    uint32_t* VsB = dsm + 2 * 64 * KST;
    uint32_t* Es  = VsB + 2 * 64 * KST;
    float*    red = (float*)(Es + 64 * KST);

    const int b = blockIdx.z, h = blockIdx.y;
    const int q0 = blockIdx.x * 64;
    const int tid = threadIdx.x;
    const int wid = tid >> 5, lane = tid & 31;
    const int g = lane >> 2, t = lane & 3;
    const int wm = (wid & 3) * 16;
    const int wn = (wid >> 2) * 32;
    const size_t bh = (size_t)(b * NH + h);

    const int sr = tid >> 2;
    const int sch = tid & 3;

    const __half* qptr = g_q + (bh * NS + q0) * NDH;
    cpa16(&Es[sr * KST + sch * 4],      qptr + sr * NDH + sch * 8);
    cpa16(&Es[sr * KST + sch * 4 + 16], qptr + sr * NDH + sch * 8 + 32);
    cpa_commit();
    cpa_wait0();
    __syncthreads();

    uint32_t qf[4][4];
#pragma unroll
    for (int ch = 0; ch < 4; ch++) {
        qf[ch][0] = Es[(wm + g)     * KST + ch * 8 + t];
        qf[ch][1] = Es[(wm + g + 8) * KST + ch * 8 + t];
        qf[ch][2] = Es[(wm + g)     * KST + ch * 8 + t + 4];
        qf[ch][3] = Es[(wm + g + 8) * KST + ch * 8 + t + 4];
    }
    __syncthreads();

    float cacc[4][4];
#pragma unroll
    for (int nt = 0; nt < 4; nt++)
#pragma unroll
        for (int q = 0; q < 4; q++) cacc[nt][q] = 0.f;
    float rs0 = 0.f, rs1 = 0.f;

    const int* mbase = mask + (size_t)b * NS * NS;
    __half* ewbase = g_ew + bh * NS * NS;
    const __half* kbase = g_k + bh * NS * NDH;
    const __half* vbase = g_v + bh * (size_t)NDH * NS;

    cpa16(&KsB[sr * KST + sch * 4],      kbase + sr * NDH + sch * 8);
    cpa16(&KsB[sr * KST + sch * 4 + 16], kbase + sr * NDH + sch * 8 + 32);
    cpa16(&VsB[sr * KST + sch * 4],      vbase + (size_t)sr * NS + sch * 8);
    cpa16(&VsB[sr * KST + sch * 4 + 16], vbase + (size_t)sr * NS + sch * 8 + 32);
    cpa_commit();

    for (int kt = 0; kt < NT_TILES; kt++) {
        if (kt + 1 < NT_TILES) {
            const int nb = (kt + 1) & 1;
            const __half* kp = kbase + (size_t)(kt + 1) * 64 * NDH;
            const __half* vp = vbase + (size_t)(kt + 1) * 64;
            uint32_t* kd = KsB + nb * 64 * KST;
            uint32_t* vd = VsB + nb * 64 * KST;
            cpa16(&kd[sr * KST + sch * 4],      kp + sr * NDH + sch * 8);
            cpa16(&kd[sr * KST + sch * 4 + 16], kp + sr * NDH + sch * 8 + 32);
            cpa16(&vd[sr * KST + sch * 4],      vp + (size_t)sr * NS + sch * 8);
            cpa16(&vd[sr * KST + sch * 4 + 16], vp + (size_t)sr * NS + sch * 8 + 32);
            cpa_commit();
            cpa_wait1();
        } else {
            cpa_wait0();
        }
        __syncthreads();

        const uint32_t* Ks = KsB + (kt & 1) * 64 * KST;
        const uint32_t* Vs = VsB + (kt & 1) * 64 * KST;

        float lg[4][4];
#pragma unroll
        for (int nt = 0; nt < 4; nt++)
#pragma unroll
            for (int q = 0; q < 4; q++) lg[nt][q] = 0.f;
#pragma unroll
        for (int ch = 0; ch < 4; ch++) {
#pragma unroll
            for (int nt = 0; nt < 4; nt++) {
                const int kc = wn + nt * 8;
                uint32_t bf[2];
                bf[0] = Ks[(kc + g) * KST + ch * 8 + t];
                bf[1] = Ks[(kc + g) * KST + ch * 8 + t + 4];
                mma_f16(lg[nt], qf[ch], bf);
            }
        }

        const int qr0 = q0 + wm + g, qr1 = qr0 + 8;
#pragma unroll
        for (int nt = 0; nt < 4; nt++) {
            const int klocal = wn + nt * 8 + 2 * t;
            const int kcg = kt * 64 + klocal;
            int2 m0 = *(const int2*)(mbase + (size_t)qr0 * NS + kcg);
            int2 m1 = *(const int2*)(mbase + (size_t)qr1 * NS + kcg);
            float e0 = m0.x ? 0.f : __expf(lg[nt][0] * 0.125f);
            float e1 = m0.y ? 0.f : __expf(lg[nt][1] * 0.125f);
            float e2 = m1.x ? 0.f : __expf(lg[nt][2] * 0.125f);
            float e3 = m1.y ? 0.f : __expf(lg[nt][3] * 0.125f);
            rs0 += e0 + e1;
            rs1 += e2 + e3;
            const uint32_t p01 = f2h2(e0, e1);
            const uint32_t p23 = f2h2(e2, e3);
            if (store_w) {
                *(uint32_t*)&ewbase[(size_t)qr0 * NS + kcg] = p01;
                *(uint32_t*)&ewbase[(size_t)qr1 * NS + kcg] = p23;
            }
            const int pair = (klocal >> 1);
            Es[(wm + g)     * KST + pair] = p01;
            Es[(wm + g + 8) * KST + pair] = p23;
        }
        __syncthreads();

#pragma unroll
        for (int ch = 0; ch < 4; ch++) {
            uint32_t af[4];
            af[0] = Es[(wm + g)     * KST + ch * 8 + t];
            af[1] = Es[(wm + g + 8) * KST + ch * 8 + t];
            af[2] = Es[(wm + g)     * KST + ch * 8 + t + 4];
            af[3] = Es[(wm + g + 8) * KST + ch * 8 + t + 4];
#pragma unroll
            for (int nt = 0; nt < 4; nt++) {
                const int dc = wn + nt * 8 + g;
                uint32_t bf[2];
                bf[0] = Vs[dc * KST + ch * 8 + t];
                bf[1] = Vs[dc * KST + ch * 8 + t + 4];
                mma_f16(cacc[nt], af, bf);
            }
        }
        __syncthreads();
    }

    rs0 += __shfl_xor_sync(0xffffffffu, rs0, 1);
    rs0 += __shfl_xor_sync(0xffffffffu, rs0, 2);
    rs1 += __shfl_xor_sync(0xffffffffu, rs1, 1);
    rs1 += __shfl_xor_sync(0xffffffffu, rs1, 2);
    if (t == 0) {
        const int half = (wid >= 4) ? 64 : 0;
        red[half + wm + g]     = rs0;
        red[half + wm + g + 8] = rs1;
    }
    __syncthreads();
    const float tot0 = red[wm + g]     + red[64 + wm + g];
    const float tot1 = red[wm + g + 8] + red[64 + wm + g + 8];
    if (wid < 4 && t == 0) {
        g_rowsum[bh * NS + q0 + wm + g]     = tot0;
        g_rowsum[bh * NS + q0 + wm + g + 8] = tot1;
    }
    const float inv0 = 1.f / tot0, inv1 = 1.f / tot1;

    const int q = q0 + wm + g;
#pragma unroll
    for (int nt = 0; nt < 4; nt++) {
        const int dh = wn + nt * 8 + 2 * t;
        *(uint32_t*)&g_attn[((size_t)b * NS + q) * ND + h * NDH + dh] =
            f2h2(cacc[nt][0] * inv0, cacc[nt][1] * inv0);
        *(uint32_t*)&g_attn[((size_t)b * NS + q + 8) * ND + h * NDH + dh] =
            f2h2(cacc[nt][2] * inv1, cacc[nt][3] * inv1);
    }
}

// Normalize: w[row][k] = float(ew_fp16[row][k]) * (1/rowsum[row])
// Reads 268 MB fp16, writes 537 MB f32 — 805 MB total vs old 1.07 GB.
__global__ __launch_bounds__(128) void norm_w(float* __restrict__ w)
{
    const int row = blockIdx.x;
    const float inv = 1.f / g_rowsum[row];
    const uint2* s = (const uint2*)(g_ew + (size_t)row * NS);   // 4 halves / uint2
    float4* d = (float4*)(w + (size_t)row * NS);
#pragma unroll
    for (int i = threadIdx.x; i < NS / 4; i += 128) {
        uint2 pk = s[i];
        __half2 h0 = *reinterpret_cast<__half2*>(&pk.x);
        __half2 h1 = *reinterpret_cast<__half2*>(&pk.y);
        float2 f0 = __half22float2(h0);
        float2 f1 = __half22float2(h1);
        d[i] = make_float4(f0.x * inv, f0.y * inv, f1.x * inv, f1.y * inv);
    }
}

extern "C" void kernel_launch(void* const* d_in, const int* in_sizes, int n_in,
                              void* d_out, int out_size)
{
    const float* Xq  = (const float*)d_in[0];
    const float* Xk  = (const float*)d_in[1];
    const float* Xv  = (const float*)d_in[2];
    const int*   msk = (const int*)d_in[3];
    const float* Wq  = (const float*)d_in[4];
    const float* bq  = (const float*)d_in[5];
    const float* Wk  = (const float*)d_in[6];
    const float* bk  = (const float*)d_in[7];
    const float* Wv  = (const float*)d_in[8];
    const float* bv  = (const float*)d_in[9];
    const float* Wo  = (const float*)d_in[10];
    const float* bo  = (const float*)d_in[11];

    float* out = (float*)d_out;
    const size_t n_attn = (size_t)NB * NS * ND;
    const size_t n_w    = (size_t)NB * NH * NS * NS;

    float* attn_dst = nullptr;
    float* w_dst = nullptr;
    if ((size_t)out_size >= n_attn + n_w) { attn_dst = out; w_dst = out + n_attn; }
    else if ((size_t)out_size >= n_w)     { w_dst = out; }
    else                                  { attn_dst = out; }

    __half *pxh, *pwh, *pq, *pk, *pv, *pa;
    cudaGetSymbolAddress((void**)&pxh, g_xh);
    cudaGetSymbolAddress((void**)&pwh, g_wh);
    cudaGetSymbolAddress((void**)&pq, g_q);
    cudaGetSymbolAddress((void**)&pk, g_k);
    cudaGetSymbolAddress((void**)&pv, g_v);
    cudaGetSymbolAddress((void**)&pa, g_attn);

    const size_t xN = (size_t)NM * ND;
    const size_t wN = (size_t)ND * ND;

    // 1) Convert inputs + weights to fp16
    CvtArgs ca;
    ca.s[0] = Xq; ca.d[0] = pxh + 0 * xN; ca.n4[0] = (int)(xN / 4);
    ca.s[1] = Xk; ca.d[1] = pxh + 1 * xN; ca.n4[1] = (int)(xN / 4);
    ca.s[2] = Xv; ca.d[2] = pxh + 2 * xN; ca.n4[2] = (int)(xN / 4);
    ca.s[3] = Wq; ca.d[3] = pwh + 0 * wN; ca.n4[3] = (int)(wN / 4);
    ca.s[4] = Wk; ca.d[4] = pwh + 1 * wN; ca.n4[4] = (int)(wN / 4);
    ca.s[5] = Wv; ca.d[5] = pwh + 2 * wN; ca.n4[5] = (int)(wN / 4);
    ca.s[6] = Wo; ca.d[6] = pwh + 3 * wN; ca.n4[6] = (int)(wN / 4);
    cvt_f2h<<<dim3(1024, 7), 256>>>(ca);

    // 2) Batched Q/K/V projections
    P3h p;
    p.A[0] = pxh + 0 * xN; p.W[0] = pwh + 0 * wN; p.B[0] = bq; p.O[0] = pq;
    p.A[1] = pxh + 1 * xN; p.W[1] = pwh + 1 * wN; p.B[1] = bk; p.O[1] = pk;
    p.A[2] = pxh + 2 * xN; p.W[2] = pwh + 2 * wN; p.B[2] = bv; p.O[2] = pv;
    gemm_qkv<<<dim3(ND / 128, NM / 128, 3), 256>>>(p);

    // 3) Attention (stores fp16 unnormalized weights to g_ew)
    const int attn_smem = (5 * 64 * KST) * 4 + 128 * 4 + 256;
    cudaFuncSetAttribute(attn_f16, cudaFuncAttributeMaxDynamicSharedMemorySize, attn_smem);
    attn_f16<<<dim3(NS / 64, NH, NB), 256, attn_smem>>>(msk, w_dst ? 1 : 0);

    // 4) norm_w (DRAM-bound) overlapped with output projection (compute-bound)
    dim3 ggrid(ND / 128, NM / 128);
    if (w_dst && attn_dst) {
        cudaStream_t s2;
        cudaStreamCreateWithFlags(&s2, cudaStreamNonBlocking);
        cudaEvent_t e1, e2;
        cudaEventCreateWithFlags(&e1, cudaEventDisableTiming);
        cudaEventCreateWithFlags(&e2, cudaEventDisableTiming);
        cudaEventRecord(e1, 0);
        cudaStreamWaitEvent(s2, e1, 0);
        norm_w<<<NB * NH * NS, 128, 0, s2>>>(w_dst);
        gemm_out<<<ggrid, 256>>>(pa, pwh + 3 * wN, bo, attn_dst);
        cudaEventRecord(e2, s2);
        cudaStreamWaitEvent(0, e2, 0);
    } else {
        if (w_dst) norm_w<<<NB * NH * NS, 128>>>(w_dst);
        if (attn_dst) gemm_out<<<ggrid, 256>>>(pa, pwh + 3 * wN, bo, attn_dst);
    }
}

// round 14
// speedup vs baseline: 1.5963x; 1.0988x over previous
#include <cuda_runtime.h>
#include <cuda_fp16.h>
#include <cstdint>

// Problem constants
#define NB 2
#define NS 2048
#define ND 1024
#define NH 16
#define NDH 64
#define NM (NB * NS)

// Scratch (device globals: allocation-free)
__device__ __half g_xh[3][(size_t)NM * ND];            // fp16 copies of Xq,Xk,Xv
__device__ __half g_wh[4][(size_t)ND * ND];            // fp16 copies of Wq,Wk,Wv,Wo
__device__ __half g_q[(size_t)NB * NH * NS * NDH];     // [b,h,s,dh]
__device__ __half g_k[(size_t)NB * NH * NS * NDH];     // [b,h,s,dh]
__device__ __half g_v[(size_t)NB * NH * NS * NDH];     // [b,h,dh,s]  TRANSPOSED
__device__ __half g_attn[(size_t)NB * NS * ND];        // fp16 concat output
__device__ __half g_ew[(size_t)NB * NH * NS * NS];     // fp16 unnormalized weights
__device__ float  g_rowsum[(size_t)NB * NH * NS];
__device__ uint32_t g_pm[(size_t)NB * NS * (NS / 32)]; // bit-packed mask

// ---------------- helpers ----------------
__device__ __forceinline__ uint32_t f2h2(float a, float b) {
    __half2 h = __floats2half2_rn(a, b);
    return *reinterpret_cast<uint32_t*>(&h);
}

__device__ __forceinline__ void mma_f16(float c[4], const uint32_t a[4], const uint32_t b[2]) {
    asm volatile(
        "mma.sync.aligned.m16n8k16.row.col.f32.f16.f16.f32 "
        "{%0,%1,%2,%3}, {%4,%5,%6,%7}, {%8,%9}, {%0,%1,%2,%3};"
        : "+f"(c[0]), "+f"(c[1]), "+f"(c[2]), "+f"(c[3])
        : "r"(a[0]), "r"(a[1]), "r"(a[2]), "r"(a[3]), "r"(b[0]), "r"(b[1]));
}

__device__ __forceinline__ void ldm_x4(uint32_t* r, const uint32_t* p) {
    uint32_t a = (uint32_t)__cvta_generic_to_shared(p);
    asm volatile("ldmatrix.sync.aligned.m8n8.x4.shared.b16 {%0,%1,%2,%3}, [%4];"
        : "=r"(r[0]), "=r"(r[1]), "=r"(r[2]), "=r"(r[3]) : "r"(a));
}
__device__ __forceinline__ void ldm_x2(uint32_t* r, const uint32_t* p) {
    uint32_t a = (uint32_t)__cvta_generic_to_shared(p);
    asm volatile("ldmatrix.sync.aligned.m8n8.x2.shared.b16 {%0,%1}, [%2];"
        : "=r"(r[0]), "=r"(r[1]) : "r"(a));
}

__device__ __forceinline__ void cpa16(void* smem, const void* g) {
    uint32_t s = (uint32_t)__cvta_generic_to_shared(smem);
    asm volatile("cp.async.cg.shared.global [%0], [%1], 16;" :: "r"(s), "l"(g));
}
__device__ __forceinline__ void cpa_commit() { asm volatile("cp.async.commit_group;"); }
__device__ __forceinline__ void cpa_wait0() { asm volatile("cp.async.wait_group 0;" ::: "memory"); }
__device__ __forceinline__ void cpa_wait1() { asm volatile("cp.async.wait_group 1;" ::: "memory"); }

// ---------------------------------------------------------------------------
// Batched f32 -> f16 conversion
// ---------------------------------------------------------------------------
struct CvtArgs {
    const float* s[7];
    __half* d[7];
    int n4[7];
};

__global__ __launch_bounds__(256) void cvt_f2h(CvtArgs a)
{
    const int z = blockIdx.y;
    const float4* s = (const float4*)a.s[z];
    __half* d = a.d[z];
    const int n4 = a.n4[z];
    for (int i = blockIdx.x * blockDim.x + threadIdx.x; i < n4;
         i += gridDim.x * blockDim.x) {
        float4 f = s[i];
        *(uint2*)(d + (size_t)i * 4) = make_uint2(f2h2(f.x, f.y), f2h2(f.z, f.w));
    }
}

// Bit-pack the mask: bit k of word w = (mask[w*32+k] != 0)
__global__ __launch_bounds__(256) void pack_mask(const int* __restrict__ mask, int n)
{
    const int i = blockIdx.x * 256 + threadIdx.x;
    if (i < n) {
        const uint32_t b = __ballot_sync(0xffffffffu, mask[i] != 0);
        if ((threadIdx.x & 31) == 0) g_pm[i >> 5] = b;
    }
}

// ---------------------------------------------------------------------------
// fp16-input GEMM, 3-stage cp.async pipeline, ONE sync per k-stage.
// C = A(f16, MxK) @ W^T(f16, NxK) + bias(f32). BM=BN=128, BK=32, 256 thr.
// Dynamic smem: 3 stages x (A 2560 + W 2560 words) = 61,440 B.
// ---------------------------------------------------------------------------
#define HG3_ISSUE(st, k0)                                                          \
    do {                                                                           \
        uint32_t* Ab = sm3 + (st) * 2560;                                          \
        uint32_t* Wb = sm3 + 7680 + (st) * 2560;                                   \
        cpa16(&Ab[sr0 * 20 + sch * 4], abase + (size_t)sr0 * ND + (k0) + sch * 8); \
        cpa16(&Ab[sr1 * 20 + sch * 4], abase + (size_t)sr1 * ND + (k0) + sch * 8); \
        cpa16(&Wb[sr0 * 20 + sch * 4], wbase + (size_t)sr0 * ND + (k0) + sch * 8); \
        cpa16(&Wb[sr1 * 20 + sch * 4], wbase + (size_t)sr1 * ND + (k0) + sch * 8); \
        cpa_commit();                                                              \
    } while (0)

template <int MODE>   // 0: f32 row-major; 1: half [b,h,s,dh]; 2: half [b,h,dh,s]
__device__ __forceinline__ void hgemm3_body(
    const __half* __restrict__ A, const __half* __restrict__ W,
    const float* __restrict__ bias, void* __restrict__ outv,
    int bm, int bn, uint32_t* sm3)
{
    const int tid = threadIdx.x;
    const int wid = tid >> 5, lane = tid & 31;
    const int g = lane >> 2, t = lane & 3;
    const int wm = (wid & 3) * 32;
    const int wn = (wid >> 2) * 64;

    const int sr0 = tid >> 2, sr1 = sr0 + 64;
    const int sch = tid & 3;

    const int la16 = lane & 15;
    const int lac  = (lane >> 4) * 4;
    const int lb8  = lane & 7;
    const int lbc  = ((lane >> 3) & 1) * 4;

    float c[2][8][4];
#pragma unroll
    for (int i = 0; i < 2; i++)
#pragma unroll
        for (int j = 0; j < 8; j++)
#pragma unroll
            for (int q = 0; q < 4; q++) c[i][j][q] = 0.f;

    const __half* abase = A + (size_t)bm * ND;
    const __half* wbase = W + (size_t)bn * ND;

    HG3_ISSUE(0, 0);
    HG3_ISSUE(1, 32);

    for (int s = 0; s < 32; s++) {
        if (s < 31) cpa_wait1(); else cpa_wait0();
        __syncthreads();                       // stage s visible; stage s-1 compute done
        if (s + 2 < 32) HG3_ISSUE((s + 2) % 3, (s + 2) * 32);

        const uint32_t* Ab = sm3 + (s % 3) * 2560;
        const uint32_t* Wb = sm3 + 7680 + (s % 3) * 2560;
#pragma unroll
        for (int ch = 0; ch < 2; ch++) {
            uint32_t af[2][4];
            ldm_x4(af[0], &Ab[(wm + la16)      * 20 + ch * 8 + lac]);
            ldm_x4(af[1], &Ab[(wm + 16 + la16) * 20 + ch * 8 + lac]);
#pragma unroll
            for (int nt = 0; nt < 8; nt++) {
                uint32_t bf[2];
                ldm_x2(bf, &Wb[(wn + nt * 8 + lb8) * 20 + ch * 8 + lbc]);
                mma_f16(c[0][nt], af[0], bf);
                mma_f16(c[1][nt], af[1], bf);
            }
        }
    }

#pragma unroll
    for (int mt = 0; mt < 2; mt++) {
#pragma unroll
        for (int rr = 0; rr < 2; rr++) {
            const int m = bm + wm + mt * 16 + g + rr * 8;
            const int b = m >> 11, sIdx = m & (NS - 1);
#pragma unroll
            for (int nt = 0; nt < 8; nt++) {
                const int col = bn + wn + nt * 8 + 2 * t;
                const float vx = c[mt][nt][rr * 2 + 0] + bias[col];
                const float vy = c[mt][nt][rr * 2 + 1] + bias[col + 1];
                if (MODE == 0) {
                    *(float2*)&((float*)outv)[(size_t)m * ND + col] = make_float2(vx, vy);
                } else if (MODE == 1) {
                    const int h = col >> 6, dh = col & 63;
                    *(uint32_t*)&((__half*)outv)[((size_t)(b * NH + h) * NS + sIdx) * NDH + dh] =
                        f2h2(vx, vy);
                } else {
                    const int h = col >> 6, dh = col & 63;
                    __half* o = (__half*)outv + ((size_t)(b * NH + h) * NDH) * NS;
                    o[(size_t)dh * NS + sIdx]       = __float2half_rn(vx);
                    o[(size_t)(dh + 1) * NS + sIdx] = __float2half_rn(vy);
                }
            }
        }
    }
}

struct P3h {
    const __half* A[3];
    const __half* W[3];
    const float* B[3];
    __half* O[3];
};

__global__ __launch_bounds__(256) void gemm_qkv(P3h p)
{
    extern __shared__ uint32_t sm3[];
    const int z = blockIdx.z;
    if (z != 2)
        hgemm3_body<1>(p.A[z], p.W[z], p.B[z], p.O[z],
                       blockIdx.y * 128, blockIdx.x * 128, sm3);
    else
        hgemm3_body<2>(p.A[z], p.W[z], p.B[z], p.O[z],
                       blockIdx.y * 128, blockIdx.x * 128, sm3);
}

__global__ __launch_bounds__(256) void gemm_out(
    const __half* __restrict__ A, const __half* __restrict__ W,
    const float* __restrict__ bias, float* __restrict__ out)
{
    extern __shared__ uint32_t sm3[];
    hgemm3_body<0>(A, W, bias, out, blockIdx.y * 128, blockIdx.x * 128, sm3);
}

// ---------------------------------------------------------------------------
// Attention (v7 core + bit-packed mask loads). fp16 weights to g_ew.
// ---------------------------------------------------------------------------
#define NT_TILES (NS / 64)
#define KST 36
__global__ __launch_bounds__(256) void attn_f16(int store_w)
{
    extern __shared__ uint32_t dsm[];
    uint32_t* KsB = dsm;
    uint32_t* VsB = dsm + 2 * 64 * KST;
    uint32_t* Es  = VsB + 2 * 64 * KST;
    float*    red = (float*)(Es + 64 * KST);

    const int b = blockIdx.z, h = blockIdx.y;
    const int q0 = blockIdx.x * 64;
    const int tid = threadIdx.x;
    const int wid = tid >> 5, lane = tid & 31;
    const int g = lane >> 2, t = lane & 3;
    const int wm = (wid & 3) * 16;
    const int wn = (wid >> 2) * 32;
    const size_t bh = (size_t)(b * NH + h);

    const int sr = tid >> 2;
    const int sch = tid & 3;

    const __half* qptr = g_q + (bh * NS + q0) * NDH;
    cpa16(&Es[sr * KST + sch * 4],      qptr + sr * NDH + sch * 8);
    cpa16(&Es[sr * KST + sch * 4 + 16], qptr + sr * NDH + sch * 8 + 32);
    cpa_commit();
    cpa_wait0();
    __syncthreads();

    uint32_t qf[4][4];
#pragma unroll
    for (int ch = 0; ch < 4; ch++) {
        qf[ch][0] = Es[(wm + g)     * KST + ch * 8 + t];
        qf[ch][1] = Es[(wm + g + 8) * KST + ch * 8 + t];
        qf[ch][2] = Es[(wm + g)     * KST + ch * 8 + t + 4];
        qf[ch][3] = Es[(wm + g + 8) * KST + ch * 8 + t + 4];
    }
    __syncthreads();

    float cacc[4][4];
#pragma unroll
    for (int nt = 0; nt < 4; nt++)
#pragma unroll
        for (int q = 0; q < 4; q++) cacc[nt][q] = 0.f;
    float rs0 = 0.f, rs1 = 0.f;

    const uint32_t* pmb = g_pm + (size_t)b * NS * (NS / 32);
    __half* ewbase = g_ew + bh * NS * NS;
    const __half* kbase = g_k + bh * NS * NDH;
    const __half* vbase = g_v + bh * (size_t)NDH * NS;

    const int qr0 = q0 + wm + g, qr1 = qr0 + 8;

    cpa16(&KsB[sr * KST + sch * 4],      kbase + sr * NDH + sch * 8);
    cpa16(&KsB[sr * KST + sch * 4 + 16], kbase + sr * NDH + sch * 8 + 32);
    cpa16(&VsB[sr * KST + sch * 4],      vbase + (size_t)sr * NS + sch * 8);
    cpa16(&VsB[sr * KST + sch * 4 + 16], vbase + (size_t)sr * NS + sch * 8 + 32);
    cpa_commit();

    for (int kt = 0; kt < NT_TILES; kt++) {
        if (kt + 1 < NT_TILES) {
            const int nb = (kt + 1) & 1;
            const __half* kp = kbase + (size_t)(kt + 1) * 64 * NDH;
            const __half* vp = vbase + (size_t)(kt + 1) * 64;
            uint32_t* kd = KsB + nb * 64 * KST;
            uint32_t* vd = VsB + nb * 64 * KST;
            cpa16(&kd[sr * KST + sch * 4],      kp + sr * NDH + sch * 8);
            cpa16(&kd[sr * KST + sch * 4 + 16], kp + sr * NDH + sch * 8 + 32);
            cpa16(&vd[sr * KST + sch * 4],      vp + (size_t)sr * NS + sch * 8);
            cpa16(&vd[sr * KST + sch * 4 + 16], vp + (size_t)sr * NS + sch * 8 + 32);
            cpa_commit();
            cpa_wait1();
        } else {
            cpa_wait0();
        }
        __syncthreads();

        const uint32_t* Ks = KsB + (kt & 1) * 64 * KST;
        const uint32_t* Vs = VsB + (kt & 1) * 64 * KST;

        float lg[4][4];
#pragma unroll
        for (int nt = 0; nt < 4; nt++)
#pragma unroll
            for (int q = 0; q < 4; q++) lg[nt][q] = 0.f;
#pragma unroll
        for (int ch = 0; ch < 4; ch++) {
#pragma unroll
            for (int nt = 0; nt < 4; nt++) {
                const int kc = wn + nt * 8;
                uint32_t bf[2];
                bf[0] = Ks[(kc + g) * KST + ch * 8 + t];
                bf[1] = Ks[(kc + g) * KST + ch * 8 + t + 4];
                mma_f16(lg[nt], qf[ch], bf);
            }
        }

        // Bit-packed mask: one 32-key word per row per tile
        const int wrow = (kt * 64 + wn) >> 5;
        const uint32_t mw0 = pmb[(size_t)qr0 * (NS / 32) + wrow];
        const uint32_t mw1 = pmb[(size_t)qr1 * (NS / 32) + wrow];

#pragma unroll
        for (int nt = 0; nt < 4; nt++) {
            const int klocal = wn + nt * 8 + 2 * t;
            const int kcg = kt * 64 + klocal;
            const int sh = nt * 8 + 2 * t;
            float e0 = (mw0 >> sh) & 1        ? 0.f : __expf(lg[nt][0] * 0.125f);
            float e1 = (mw0 >> (sh + 1)) & 1  ? 0.f : __expf(lg[nt][1] * 0.125f);
            float e2 = (mw1 >> sh) & 1        ? 0.f : __expf(lg[nt][2] * 0.125f);
            float e3 = (mw1 >> (sh + 1)) & 1  ? 0.f : __expf(lg[nt][3] * 0.125f);
            rs0 += e0 + e1;
            rs1 += e2 + e3;
            const uint32_t p01 = f2h2(e0, e1);
            const uint32_t p23 = f2h2(e2, e3);
            if (store_w) {
                *(uint32_t*)&ewbase[(size_t)qr0 * NS + kcg] = p01;
                *(uint32_t*)&ewbase[(size_t)qr1 * NS + kcg] = p23;
            }
            const int pair = (klocal >> 1);
            Es[(wm + g)     * KST + pair] = p01;
            Es[(wm + g + 8) * KST + pair] = p23;
        }
        __syncthreads();

#pragma unroll
        for (int ch = 0; ch < 4; ch++) {
            uint32_t af[4];
            af[0] = Es[(wm + g)     * KST + ch * 8 + t];
            af[1] = Es[(wm + g + 8) * KST + ch * 8 + t];
            af[2] = Es[(wm + g)     * KST + ch * 8 + t + 4];
            af[3] = Es[(wm + g + 8) * KST + ch * 8 + t + 4];
#pragma unroll
            for (int nt = 0; nt < 4; nt++) {
                const int dc = wn + nt * 8 + g;
                uint32_t bf[2];
                bf[0] = Vs[dc * KST + ch * 8 + t];
                bf[1] = Vs[dc * KST + ch * 8 + t + 4];
                mma_f16(cacc[nt], af, bf);
            }
        }
        __syncthreads();
    }

    rs0 += __shfl_xor_sync(0xffffffffu, rs0, 1);
    rs0 += __shfl_xor_sync(0xffffffffu, rs0, 2);
    rs1 += __shfl_xor_sync(0xffffffffu, rs1, 1);
    rs1 += __shfl_xor_sync(0xffffffffu, rs1, 2);
    if (t == 0) {
        const int half = (wid >= 4) ? 64 : 0;
        red[half + wm + g]     = rs0;
        red[half + wm + g + 8] = rs1;
    }
    __syncthreads();
    const float tot0 = red[wm + g]     + red[64 + wm + g];
    const float tot1 = red[wm + g + 8] + red[64 + wm + g + 8];
    if (wid < 4 && t == 0) {
        g_rowsum[bh * NS + q0 + wm + g]     = tot0;
        g_rowsum[bh * NS + q0 + wm + g + 8] = tot1;
    }
    const float inv0 = 1.f / tot0, inv1 = 1.f / tot1;

    const int q = q0 + wm + g;
#pragma unroll
    for (int nt = 0; nt < 4; nt++) {
        const int dh = wn + nt * 8 + 2 * t;
        *(uint32_t*)&g_attn[((size_t)b * NS + q) * ND + h * NDH + dh] =
            f2h2(cacc[nt][0] * inv0, cacc[nt][1] * inv0);
        *(uint32_t*)&g_attn[((size_t)b * NS + q + 8) * ND + h * NDH + dh] =
            f2h2(cacc[nt][2] * inv1, cacc[nt][3] * inv1);
    }
}

// Normalize: w[row][k] = float(ew_fp16[row][k]) * (1/rowsum[row])
__global__ __launch_bounds__(128) void norm_w(float* __restrict__ w)
{
    const int row = blockIdx.x;
    const float inv = 1.f / g_rowsum[row];
    const uint2* s = (const uint2*)(g_ew + (size_t)row * NS);
    float4* d = (float4*)(w + (size_t)row * NS);
#pragma unroll
    for (int i = threadIdx.x; i < NS / 4; i += 128) {
        uint2 pk = s[i];
        __half2 h0 = *reinterpret_cast<__half2*>(&pk.x);
        __half2 h1 = *reinterpret_cast<__half2*>(&pk.y);
        float2 f0 = __half22float2(h0);
        float2 f1 = __half22float2(h1);
        d[i] = make_float4(f0.x * inv, f0.y * inv, f1.x * inv, f1.y * inv);
    }
}

extern "C" void kernel_launch(void* const* d_in, const int* in_sizes, int n_in,
                              void* d_out, int out_size)
{
    const float* Xq  = (const float*)d_in[0];
    const float* Xk  = (const float*)d_in[1];
    const float* Xv  = (const float*)d_in[2];
    const int*   msk = (const int*)d_in[3];
    const float* Wq  = (const float*)d_in[4];
    const float* bq  = (const float*)d_in[5];
    const float* Wk  = (const float*)d_in[6];
    const float* bk  = (const float*)d_in[7];
    const float* Wv  = (const float*)d_in[8];
    const float* bv  = (const float*)d_in[9];
    const float* Wo  = (const float*)d_in[10];
    const float* bo  = (const float*)d_in[11];

    float* out = (float*)d_out;
    const size_t n_attn = (size_t)NB * NS * ND;
    const size_t n_w    = (size_t)NB * NH * NS * NS;

    float* attn_dst = nullptr;
    float* w_dst = nullptr;
    if ((size_t)out_size >= n_attn + n_w) { attn_dst = out; w_dst = out + n_attn; }
    else if ((size_t)out_size >= n_w)     { w_dst = out; }
    else                                  { attn_dst = out; }

    __half *pxh, *pwh, *pq, *pk, *pv, *pa;
    cudaGetSymbolAddress((void**)&pxh, g_xh);
    cudaGetSymbolAddress((void**)&pwh, g_wh);
    cudaGetSymbolAddress((void**)&pq, g_q);
    cudaGetSymbolAddress((void**)&pk, g_k);
    cudaGetSymbolAddress((void**)&pv, g_v);
    cudaGetSymbolAddress((void**)&pa, g_attn);

    const size_t xN = (size_t)NM * ND;
    const size_t wN = (size_t)ND * ND;

    cudaStream_t s2;
    cudaStreamCreateWithFlags(&s2, cudaStreamNonBlocking);
    cudaEvent_t eA, eB, eC, eD;
    cudaEventCreateWithFlags(&eA, cudaEventDisableTiming);
    cudaEventCreateWithFlags(&eB, cudaEventDisableTiming);
    cudaEventCreateWithFlags(&eC, cudaEventDisableTiming);
    cudaEventCreateWithFlags(&eD, cudaEventDisableTiming);

    // Fork 1: pack_mask (independent) overlaps cvt + qkv
    cudaEventRecord(eA, 0);
    cudaStreamWaitEvent(s2, eA, 0);
    {
        const int n = NB * NS * NS;
        pack_mask<<<(n + 255) / 256, 256, 0, s2>>>(msk, n);
    }

    // 1) Convert inputs + weights to fp16
    CvtArgs ca;
    ca.s[0] = Xq; ca.d[0] = pxh + 0 * xN; ca.n4[0] = (int)(xN / 4);
    ca.s[1] = Xk; ca.d[1] = pxh + 1 * xN; ca.n4[1] = (int)(xN / 4);
    ca.s[2] = Xv; ca.d[2] = pxh + 2 * xN; ca.n4[2] = (int)(xN / 4);
    ca.s[3] = Wq; ca.d[3] = pwh + 0 * wN; ca.n4[3] = (int)(wN / 4);
    ca.s[4] = Wk; ca.d[4] = pwh + 1 * wN; ca.n4[4] = (int)(wN / 4);
    ca.s[5] = Wv; ca.d[5] = pwh + 2 * wN; ca.n4[5] = (int)(wN / 4);
    ca.s[6] = Wo; ca.d[6] = pwh + 3 * wN; ca.n4[6] = (int)(wN / 4);
    cvt_f2h<<<dim3(1024, 7), 256>>>(ca);

    // 2) Batched Q/K/V projections (3-stage pipeline, 61,440 B dyn smem)
    const int g3_smem = 15360 * 4;
    cudaFuncSetAttribute(gemm_qkv, cudaFuncAttributeMaxDynamicSharedMemorySize, g3_smem);
    cudaFuncSetAttribute(gemm_out, cudaFuncAttributeMaxDynamicSharedMemorySize, g3_smem);
    P3h p;
    p.A[0] = pxh + 0 * xN; p.W[0] = pwh + 0 * wN; p.B[0] = bq; p.O[0] = pq;
    p.A[1] = pxh + 1 * xN; p.W[1] = pwh + 1 * wN; p.B[1] = bk; p.O[1] = pk;
    p.A[2] = pxh + 2 * xN; p.W[2] = pwh + 2 * wN; p.B[2] = bv; p.O[2] = pv;
    gemm_qkv<<<dim3(ND / 128, NM / 128, 3), 256, g3_smem>>>(p);

    // Join: attn needs packed mask + projections
    cudaEventRecord(eB, s2);
    cudaStreamWaitEvent(0, eB, 0);

    // 3) Attention
    const int attn_smem = (5 * 64 * KST) * 4 + 128 * 4 + 256;
    cudaFuncSetAttribute(attn_f16, cudaFuncAttributeMaxDynamicSharedMemorySize, attn_smem);
    attn_f16<<<dim3(NS / 64, NH, NB), 256, attn_smem>>>(w_dst ? 1 : 0);

    // 4) norm_w overlapped with output projection
    dim3 ggrid(ND / 128, NM / 128);
    if (w_dst && attn_dst) {
        cudaEventRecord(eC, 0);
        cudaStreamWaitEvent(s2, eC, 0);
        norm_w<<<NB * NH * NS, 128, 0, s2>>>(w_dst);
        gemm_out<<<ggrid, 256, g3_smem>>>(pa, pwh + 3 * wN, bo, attn_dst);
        cudaEventRecord(eD, s2);
        cudaStreamWaitEvent(0, eD, 0);
    } else {
        if (w_dst) norm_w<<<NB * NH * NS, 128>>>(w_dst);
        if (attn_dst) gemm_out<<<ggrid, 256, g3_smem>>>(pa, pwh + 3 * wN, bo, attn_dst);
    }
}